// round 7
// baseline (speedup 1.0000x reference)
#include <cuda_runtime.h>
#include <cuda_fp16.h>
#include <math.h>
#include <stdint.h>

#define CC 64
#define HH 64
#define WWD 64
#define NN 4096
#define BB 4
#define WSET (576 * 64)

// ---------------- scratch (static device memory; no allocs allowed) ----------
__device__ float g_buf[12u * 1024u * 1024u];

static const size_t OFF_RAW = 0;
static const size_t OFF_X1H = 1u << 20;
static const size_t OFF_X1L = 2u << 20;
static const size_t OFF_TH  = 3u << 20;   // half [B,N,C]
static const size_t OFF_PHI = 4u << 20;   // half [B,C,N]
static const size_t OFF_G   = 5u << 20;   // half [B,N,C]
static const size_t OFF_Y   = 6u << 20;
static const size_t OFF_ZH  = 7u << 20;
static const size_t OFF_ZL  = 8u << 20;
static const size_t OFF_XH  = 9u << 20;
static const size_t OFF_XL  = 10u << 20;
static const size_t OFF_WTH = 11u << 20;
static const size_t OFF_WTL = OFF_WTH + 5 * 36864;
static const size_t OFF_SC  = OFF_WTL + 5 * 36864;
static const size_t OFF_SH  = OFF_SC + 64;

// ---------------- tf32 helpers -----------------------------------------------
__device__ __forceinline__ uint32_t cvt_tf32(float f) {
    uint32_t r;
    asm("cvt.rna.tf32.f32 %0, %1;" : "=r"(r) : "f"(f));
    return r;
}

__device__ __forceinline__ void mma_tf32(float c[4], const uint32_t a[4],
                                         uint32_t b0, uint32_t b1) {
    asm volatile(
        "mma.sync.aligned.m16n8k8.row.col.f32.tf32.tf32.f32 "
        "{%0,%1,%2,%3}, {%4,%5,%6,%7}, {%8,%9}, {%0,%1,%2,%3};"
        : "+f"(c[0]), "+f"(c[1]), "+f"(c[2]), "+f"(c[3])
        : "r"(a[0]), "r"(a[1]), "r"(a[2]), "r"(a[3]), "r"(b0), "r"(b1));
}

__device__ __forceinline__ void mma_f16(float c[4], const uint32_t a[4],
                                        uint32_t b0, uint32_t b1) {
    asm volatile(
        "mma.sync.aligned.m16n8k16.row.col.f32.f16.f16.f32 "
        "{%0,%1,%2,%3}, {%4,%5,%6,%7}, {%8,%9}, {%0,%1,%2,%3};"
        : "+f"(c[0]), "+f"(c[1]), "+f"(c[2]), "+f"(c[3])
        : "r"(a[0]), "r"(a[1]), "r"(a[2]), "r"(a[3]), "r"(b0), "r"(b1));
}

// ---------------- weight prep: 5 sets -> k-major hi/lo ------------------------
__global__ void wtrans_all_kernel(
    const float* __restrict__ w0, const float* __restrict__ w1,
    const float* __restrict__ w2, const float* __restrict__ w3,
    const float* __restrict__ w4, float* __restrict__ wh, float* __restrict__ wl)
{
    int i = blockIdx.x * 256 + threadIdx.x;
    if (i >= 5 * 36864) return;
    int s = i / 36864;
    int r = i - s * 36864;
    const float* w = (s == 0) ? w0 : (s == 1) ? w1 : (s == 2) ? w2 : (s == 3) ? w3 : w4;
    int oc  = r / 576;
    int r2  = r - oc * 576;
    int ic  = r2 / 9;
    int tap = r2 - ic * 9;
    float v = w[r];
    int row  = (ic >> 3) * 72 + tap * 8 + (ic & 7);
    int didx = s * 36864 + row * 64 + oc;
    uint32_t h = cvt_tf32(v);
    wh[didx] = __uint_as_float(h);
    wl[didx] = __uint_as_float(cvt_tf32(v - __uint_as_float(h)));
}

// ---------------- split fp32 -> tf32 hi/lo (float4) ---------------------------
__global__ void split_kernel(const float4* __restrict__ in,
                             float4* __restrict__ hi, float4* __restrict__ lo)
{
    int i = blockIdx.x * 256 + threadIdx.x;
    float4 v = in[i];
    float4 h, l;
    h.x = __uint_as_float(cvt_tf32(v.x)); l.x = __uint_as_float(cvt_tf32(v.x - h.x));
    h.y = __uint_as_float(cvt_tf32(v.y)); l.y = __uint_as_float(cvt_tf32(v.y - h.y));
    h.z = __uint_as_float(cvt_tf32(v.z)); l.z = __uint_as_float(cvt_tf32(v.z - h.z));
    h.w = __uint_as_float(cvt_tf32(v.w)); l.w = __uint_as_float(cvt_tf32(v.w - h.w));
    hi[i] = h; lo[i] = l;
}

// ---------------- 3x3 conv via tf32 tensor cores (3xTF32) ---------------------
__global__ void __launch_bounds__(128) conv3x3_mma_kernel(
    const float* __restrict__ in_hi, const float* __restrict__ in_lo,
    const float* __restrict__ whi, const float* __restrict__ wlo,
    const float* __restrict__ bias0, const float* __restrict__ bias1,
    const float* __restrict__ bias2,
    float* __restrict__ out0, float* __restrict__ out1, float* __restrict__ out2,
    int trans_mask, int half_mask)
{
    extern __shared__ __align__(16) float sm[];
    float* wh_s = sm;
    float* wl_s = sm + 5184;
    float* ih_s = sm + 10368;
    float* il_s = sm + 12736;

    int s = blockIdx.z;
    const float* bias = (s == 0) ? bias0 : (s == 1) ? bias1 : bias2;
    float* out = (s == 0) ? out0 : (s == 1) ? out1 : out2;
    int trans = (trans_mask >> s) & 1;
    int ashalf = (half_mask >> s) & 1;
    const float* wh = whi + (size_t)s * WSET;
    const float* wl = wlo + (size_t)s * WSET;

    int b   = blockIdx.y;
    int y0  = blockIdx.x * 2;
    int tid = threadIdx.x;
    int w    = tid >> 5;
    int lane = tid & 31;
    int gid  = lane >> 2;
    int tig  = lane & 3;
    int wy = w >> 1;
    int wx = (w & 1) * 32;

    float c[4][4][4];
#pragma unroll
    for (int mt = 0; mt < 4; mt++)
#pragma unroll
        for (int nt = 0; nt < 4; nt++)
#pragma unroll
            for (int r = 0; r < 4; r++) c[mt][nt][r] = 0.f;

    for (int ch = 0; ch < 8; ch++) {
        __syncthreads();
        for (int i = tid; i < 1152; i += 128) {
            float4 vh = *(const float4*)(wh + ch * 4608 + i * 4);
            float4 vl = *(const float4*)(wl + ch * 4608 + i * 4);
            int r  = i >> 4;
            int c4 = (i & 15) << 2;
            *(float4*)(wh_s + r * 72 + c4) = vh;
            *(float4*)(wl_s + r * 72 + c4) = vl;
        }
        for (int i = tid; i < 2112; i += 128) {
            int icL = i / 264;
            int rem = i - icL * 264;
            int iy  = rem / 66;
            int col = rem - iy * 66;
            int gy = y0 + iy - 1;
            int gx = col - 1;
            float vh = 0.f, vl = 0.f;
            if (gy >= 0 && gy < HH && gx >= 0 && gx < WWD) {
                size_t gixd = (((size_t)(b * CC + ch * 8 + icL)) << 12) + gy * WWD + gx;
                vh = in_hi[gixd];
                vl = in_lo[gixd];
            }
            ih_s[icL * 296 + iy * 72 + col] = vh;
            il_s[icL * 296 + iy * 72 + col] = vl;
        }
        __syncthreads();

#pragma unroll
        for (int kk = 0; kk < 9; kk++) {
            int ky = kk / 3, kx = kk - ky * 3;
            uint32_t bh0[4], bh1[4], bl0[4], bl1[4];
#pragma unroll
            for (int nt = 0; nt < 4; nt++) {
                int base = tig * 296 + (ky + wy) * 72 + kx + wx + nt * 8 + gid;
                bh0[nt] = __float_as_uint(ih_s[base]);
                bh1[nt] = __float_as_uint(ih_s[base + 4 * 296]);
                bl0[nt] = __float_as_uint(il_s[base]);
                bl1[nt] = __float_as_uint(il_s[base + 4 * 296]);
            }
#pragma unroll
            for (int mt = 0; mt < 4; mt++) {
                int colA = mt * 16 + gid;
                int r0 = (kk * 8 + tig) * 72;
                int r1 = (kk * 8 + tig + 4) * 72;
                uint32_t ah[4], al[4];
                ah[0] = __float_as_uint(wh_s[r0 + colA]);
                ah[1] = __float_as_uint(wh_s[r0 + colA + 8]);
                ah[2] = __float_as_uint(wh_s[r1 + colA]);
                ah[3] = __float_as_uint(wh_s[r1 + colA + 8]);
                al[0] = __float_as_uint(wl_s[r0 + colA]);
                al[1] = __float_as_uint(wl_s[r0 + colA + 8]);
                al[2] = __float_as_uint(wl_s[r1 + colA]);
                al[3] = __float_as_uint(wl_s[r1 + colA + 8]);
#pragma unroll
                for (int nt = 0; nt < 4; nt++) {
                    mma_tf32(c[mt][nt], ah, bh0[nt], bh1[nt]);
                    mma_tf32(c[mt][nt], ah, bl0[nt], bl1[nt]);
                    mma_tf32(c[mt][nt], al, bh0[nt], bh1[nt]);
                }
            }
        }
    }

    __syncthreads();
    float* Os = sm;
    float bv0[4], bv1[4];
#pragma unroll
    for (int mt = 0; mt < 4; mt++) {
        bv0[mt] = bias ? bias[mt * 16 + gid] : 0.f;
        bv1[mt] = bias ? bias[mt * 16 + gid + 8] : 0.f;
    }
#pragma unroll
    for (int mt = 0; mt < 4; mt++)
#pragma unroll
        for (int nt = 0; nt < 4; nt++) {
            int n = wx + wy * 64 + nt * 8 + 2 * tig;
            float2 v0, v1;
            v0.x = c[mt][nt][0] + bv0[mt];
            v0.y = c[mt][nt][1] + bv0[mt];
            v1.x = c[mt][nt][2] + bv1[mt];
            v1.y = c[mt][nt][3] + bv1[mt];
            *(float2*)(Os + (mt * 16 + gid) * 130 + n) = v0;
            *(float2*)(Os + (mt * 16 + gid + 8) * 130 + n) = v1;
        }
    __syncthreads();
    int n0 = blockIdx.x * 128;
    if (!trans) {
        if (ashalf) {
            __half* oh = (__half*)out;
            for (int i = tid; i < 8192; i += 128) {
                int oc = i >> 7, nl = i & 127;
                oh[(((size_t)(b * CC + oc)) << 12) + n0 + nl] = __float2half(Os[oc * 130 + nl]);
            }
        } else {
            for (int i = tid; i < 8192; i += 128) {
                int oc = i >> 7, nl = i & 127;
                out[(((size_t)(b * CC + oc)) << 12) + n0 + nl] = Os[oc * 130 + nl];
            }
        }
    } else {
        if (ashalf) {
            __half* oh = (__half*)out;
            for (int i = tid; i < 8192; i += 128) {
                int nl = i >> 6, oc = i & 63;
                oh[((size_t)b * NN + n0 + nl) * CC + oc] = __float2half(Os[oc * 130 + nl]);
            }
        } else {
            for (int i = tid; i < 8192; i += 128) {
                int nl = i >> 6, oc = i & 63;
                out[((size_t)b * NN + n0 + nl) * CC + oc] = Os[oc * 130 + nl];
            }
        }
    }
}
#define CONV_SMEM (15104 * (int)sizeof(float))

// ---------------- BN stats (float4) -------------------------------------------
__global__ void bn_stats_kernel(const float* __restrict__ in,
                                const float* __restrict__ gamma,
                                const float* __restrict__ beta,
                                float* __restrict__ scale, float* __restrict__ shift)
{
    int c = blockIdx.x;
    int tid = threadIdx.x;
    float s = 0.f, s2 = 0.f;
    for (int b = 0; b < BB; b++) {
        const float4* p4 = (const float4*)(in + (((size_t)(b * CC + c)) << 12));
        for (int i = tid; i < 1024; i += 256) {
            float4 v = p4[i];
            s += v.x + v.y + v.z + v.w;
            s2 += v.x * v.x + v.y * v.y + v.z * v.z + v.w * v.w;
        }
    }
    __shared__ float sh[256], sh2[256];
    sh[tid] = s; sh2[tid] = s2;
    __syncthreads();
    for (int o = 128; o > 0; o >>= 1) {
        if (tid < o) { sh[tid] += sh[tid + o]; sh2[tid] += sh2[tid + o]; }
        __syncthreads();
    }
    if (tid == 0) {
        const float inv = 1.f / (float)(BB * NN);
        float mean = sh[0] * inv;
        float var  = sh2[0] * inv - mean * mean;
        float r    = rsqrtf(var + 1e-5f);
        float sc   = gamma[c] * r;
        scale[c] = sc;
        shift[c] = beta[c] - mean * sc;
    }
}

__global__ void bn_apply_relu_kernel(const float4* __restrict__ in,
                                     const float* __restrict__ scale,
                                     const float* __restrict__ shift,
                                     float4* __restrict__ out)
{
    int i = blockIdx.x * 256 + threadIdx.x;
    int c = (i >> 10) & 63;
    float sc = scale[c], sf = shift[c];
    float4 v = in[i];
    v.x = fmaxf(fmaf(v.x, sc, sf), 0.f);
    v.y = fmaxf(fmaf(v.y, sc, sf), 0.f);
    v.z = fmaxf(fmaf(v.z, sc, sf), 0.f);
    v.w = fmaxf(fmaf(v.w, sc, sf), 0.f);
    out[i] = v;
}

__global__ void bn_apply_relu_split_kernel(const float4* __restrict__ in,
                                           const float* __restrict__ scale,
                                           const float* __restrict__ shift,
                                           float4* __restrict__ hi,
                                           float4* __restrict__ lo)
{
    int i = blockIdx.x * 256 + threadIdx.x;
    int c = (i >> 10) & 63;
    float sc = scale[c], sf = shift[c];
    float4 v = in[i];
    float4 h, l;
    v.x = fmaxf(fmaf(v.x, sc, sf), 0.f);
    v.y = fmaxf(fmaf(v.y, sc, sf), 0.f);
    v.z = fmaxf(fmaf(v.z, sc, sf), 0.f);
    v.w = fmaxf(fmaf(v.w, sc, sf), 0.f);
    h.x = __uint_as_float(cvt_tf32(v.x)); l.x = __uint_as_float(cvt_tf32(v.x - h.x));
    h.y = __uint_as_float(cvt_tf32(v.y)); l.y = __uint_as_float(cvt_tf32(v.y - h.y));
    h.z = __uint_as_float(cvt_tf32(v.z)); l.z = __uint_as_float(cvt_tf32(v.z - h.z));
    h.w = __uint_as_float(cvt_tf32(v.w)); l.w = __uint_as_float(cvt_tf32(v.w - h.w));
    hi[i] = h; lo[i] = l;
}

// ---------------- flash attention, fp16 MMA (m16n8k16), Br=128 ----------------
// Qt: half [B,N,C], K: half [B,C,N], Gt: half [B,N,C] -> Y: fp32 [B,C,N]
// 256 threads = 8 warps, each warp owns 16 query rows. Bc=64 keys/iter.
// smem (uint32 = half2 cells): Ks2[32 c-pairs][72 m], Gs2[32 m-pairs][72 c],
// Ps2 per warp [16 q][36 m-pairs]. All MMA-fragment LDS conflict-free
// (pitch 72: 8*tig+gid banks; pitch 36: 4*gid+tig banks).
#define FKP 72
#define FPP 36
__global__ void __launch_bounds__(256) flash_f16_kernel(
    const __half* __restrict__ Qt, const __half* __restrict__ K,
    const __half* __restrict__ Gt, float* __restrict__ Y)
{
    extern __shared__ __align__(16) uint32_t smu[];
    uint32_t* Ks2 = smu;            // 2304
    uint32_t* Gs2 = smu + 2304;     // 2304
    uint32_t* Ps2 = smu + 4608;     // 4608
    int b   = blockIdx.y;
    int n0  = blockIdx.x * 128;
    int tid = threadIdx.x;
    int w    = tid >> 5;
    int lane = tid & 31;
    int gid  = lane >> 2;
    int tig  = lane & 3;
    uint32_t* Pw = Ps2 + w * 16 * FPP;

    // Q fragments (held in regs): a-frag pairs (c-pair idx 8kk+tig, +4)
    uint32_t aq[4][4];
    {
        const uint32_t* qb2 = (const uint32_t*)(Qt + ((size_t)b * NN + n0 + w * 16) * CC);
#pragma unroll
        for (int kk = 0; kk < 4; kk++) {
            aq[kk][0] = qb2[gid * 32 + 8 * kk + tig];
            aq[kk][1] = qb2[(gid + 8) * 32 + 8 * kk + tig];
            aq[kk][2] = qb2[gid * 32 + 8 * kk + tig + 4];
            aq[kk][3] = qb2[(gid + 8) * 32 + 8 * kk + tig + 4];
        }
    }

    float o[8][4];
#pragma unroll
    for (int nt = 0; nt < 8; nt++)
#pragma unroll
        for (int r = 0; r < 4; r++) o[nt][r] = 0.f;
    float rm0 = -1e30f, rm1 = -1e30f, rl0 = 0.f, rl1 = 0.f;

    const __half2* K2 = (const __half2*)(K + (((size_t)b * CC) << 12));
    const __half2* G2 = (const __half2*)(Gt + (size_t)b * NN * CC);

    for (int j0 = 0; j0 < NN; j0 += 64) {
        __syncthreads();
        // K: need (c,c+1) pairs fixed m. Gather two rows, repack via lo/hi.
        for (int i = tid; i < 1024; i += 256) {
            int c2 = i >> 5, m2 = i & 31;
            __half2 ha = K2[(size_t)(2 * c2) * 2048 + (j0 >> 1) + m2];
            __half2 hb = K2[(size_t)(2 * c2 + 1) * 2048 + (j0 >> 1) + m2];
            __half2 lo = __lows2half2(ha, hb);
            __half2 hi = __highs2half2(ha, hb);
            *(uint2*)(Ks2 + c2 * FKP + 2 * m2) =
                make_uint2(*(uint32_t*)&lo, *(uint32_t*)&hi);
        }
        // G: need (m,m+1) pairs fixed c.
        for (int i = tid; i < 1024; i += 256) {
            int m2 = i >> 5, c2 = i & 31;
            __half2 ha = G2[(size_t)(j0 + 2 * m2) * 32 + c2];
            __half2 hb = G2[(size_t)(j0 + 2 * m2 + 1) * 32 + c2];
            __half2 lo = __lows2half2(ha, hb);
            __half2 hi = __highs2half2(ha, hb);
            *(uint2*)(Gs2 + m2 * FKP + 2 * c2) =
                make_uint2(*(uint32_t*)&lo, *(uint32_t*)&hi);
        }
        __syncthreads();

        // ---- S = Q K : 4 k-steps x 8 n-tiles ----
        float s[8][4];
#pragma unroll
        for (int nt = 0; nt < 8; nt++)
#pragma unroll
            for (int r = 0; r < 4; r++) s[nt][r] = 0.f;
#pragma unroll
        for (int kk = 0; kk < 4; kk++) {
            const uint32_t* kr0 = Ks2 + (8 * kk + tig) * FKP + gid;
            const uint32_t* kr1 = Ks2 + (8 * kk + tig + 4) * FKP + gid;
#pragma unroll
            for (int nt = 0; nt < 8; nt++)
                mma_f16(s[nt], aq[kk], kr0[8 * nt], kr1[8 * nt]);
        }

        // ---- online softmax ----
        float mx0 = -1e30f, mx1 = -1e30f;
#pragma unroll
        for (int nt = 0; nt < 8; nt++) {
            mx0 = fmaxf(mx0, fmaxf(s[nt][0], s[nt][1]));
            mx1 = fmaxf(mx1, fmaxf(s[nt][2], s[nt][3]));
        }
        mx0 = fmaxf(mx0, __shfl_xor_sync(0xffffffffu, mx0, 1));
        mx0 = fmaxf(mx0, __shfl_xor_sync(0xffffffffu, mx0, 2));
        mx1 = fmaxf(mx1, __shfl_xor_sync(0xffffffffu, mx1, 1));
        mx1 = fmaxf(mx1, __shfl_xor_sync(0xffffffffu, mx1, 2));

        float mn0 = fmaxf(rm0, mx0), mn1 = fmaxf(rm1, mx1);
        float al0 = __expf(rm0 - mn0), al1 = __expf(rm1 - mn1);
        rm0 = mn0; rm1 = mn1;

        float rs0 = 0.f, rs1 = 0.f;
#pragma unroll
        for (int nt = 0; nt < 8; nt++) {
            float p0 = __expf(s[nt][0] - mn0);
            float p1 = __expf(s[nt][1] - mn0);
            float p2 = __expf(s[nt][2] - mn1);
            float p3 = __expf(s[nt][3] - mn1);
            rs0 += p0 + p1; rs1 += p2 + p3;
            __half2 h01 = __floats2half2_rn(p0, p1);
            __half2 h23 = __floats2half2_rn(p2, p3);
            Pw[gid * FPP + 4 * nt + tig] = *(uint32_t*)&h01;
            Pw[(gid + 8) * FPP + 4 * nt + tig] = *(uint32_t*)&h23;
        }
        rs0 += __shfl_xor_sync(0xffffffffu, rs0, 1);
        rs0 += __shfl_xor_sync(0xffffffffu, rs0, 2);
        rs1 += __shfl_xor_sync(0xffffffffu, rs1, 1);
        rs1 += __shfl_xor_sync(0xffffffffu, rs1, 2);
        rl0 = rl0 * al0 + rs0;
        rl1 = rl1 * al1 + rs1;

#pragma unroll
        for (int nt = 0; nt < 8; nt++) {
            o[nt][0] *= al0; o[nt][1] *= al0;
            o[nt][2] *= al1; o[nt][3] *= al1;
        }
        __syncwarp();

        // ---- O += P G : 4 k-steps ----
#pragma unroll
        for (int kk = 0; kk < 4; kk++) {
            uint32_t pa[4];
            pa[0] = Pw[gid * FPP + 8 * kk + tig];
            pa[1] = Pw[(gid + 8) * FPP + 8 * kk + tig];
            pa[2] = Pw[gid * FPP + 8 * kk + tig + 4];
            pa[3] = Pw[(gid + 8) * FPP + 8 * kk + tig + 4];
            const uint32_t* gr0 = Gs2 + (8 * kk + tig) * FKP + gid;
            const uint32_t* gr1 = Gs2 + (8 * kk + tig + 4) * FKP + gid;
#pragma unroll
            for (int nt = 0; nt < 8; nt++)
                mma_f16(o[nt], pa, gr0[8 * nt], gr1[8 * nt]);
        }
    }

    // ---- epilogue ----
    __syncthreads();
    float li0 = 1.f / rl0, li1 = 1.f / rl1;
    float* Os = (float*)smu;   // [128][68] = 8704 floats <= 9216 avail
#pragma unroll
    for (int nt = 0; nt < 8; nt++) {
        float2 v0; v0.x = o[nt][0] * li0; v0.y = o[nt][1] * li0;
        float2 v1; v1.x = o[nt][2] * li1; v1.y = o[nt][3] * li1;
        *(float2*)(Os + (w * 16 + gid) * 68 + 8 * nt + 2 * tig) = v0;
        *(float2*)(Os + (w * 16 + gid + 8) * 68 + 8 * nt + 2 * tig) = v1;
    }
    __syncthreads();
    for (int i = tid; i < 8192; i += 256) {
        int c = i >> 7, q = i & 127;
        Y[(((size_t)(b * CC + c)) << 12) + n0 + q] = Os[q * 68 + c];
    }
}
#define FLASH_SMEM (9216 * 4)

// ---------------- 1x1 conv + bias + residual -> hi/lo split (float4) ----------
// thread: 8 oc x 4 consecutive n. grid 128 x 256 threads.
__global__ void __launch_bounds__(256) w1x1_res_kernel(
    const float* __restrict__ y, const float* __restrict__ Ww,
    const float* __restrict__ Wb, const float* __restrict__ x,
    float* __restrict__ zh, float* __restrict__ zl)
{
    __shared__ float Ws[64 * 65];
    int tid = threadIdx.x;
    for (int i = tid; i < 4096; i += 256) {
        int oc = i >> 6, ic = i & 63;
        Ws[ic * 65 + oc] = Ww[i];
    }
    __syncthreads();

    int og  = tid & 7;
    int oc0 = og * 8;
    int nl  = tid >> 3;
    int gpos = blockIdx.x * 32 + nl;          // float4 position, 0..4095
    int b = gpos >> 10, n4 = gpos & 1023;

    float4 acc[8];
#pragma unroll
    for (int j = 0; j < 8; j++) {
        float4 xv = *(const float4*)(x + (((size_t)(b * CC + oc0 + j)) << 12) + 4 * n4);
        float bvv = Wb[oc0 + j];
        acc[j].x = xv.x + bvv; acc[j].y = xv.y + bvv;
        acc[j].z = xv.z + bvv; acc[j].w = xv.w + bvv;
    }
    for (int ic = 0; ic < 64; ic++) {
        float4 v = *(const float4*)(y + (((size_t)(b * CC + ic)) << 12) + 4 * n4);
#pragma unroll
        for (int j = 0; j < 8; j++) {
            float wv = Ws[ic * 65 + oc0 + j];
            acc[j].x = fmaf(v.x, wv, acc[j].x);
            acc[j].y = fmaf(v.y, wv, acc[j].y);
            acc[j].z = fmaf(v.z, wv, acc[j].z);
            acc[j].w = fmaf(v.w, wv, acc[j].w);
        }
    }
#pragma unroll
    for (int j = 0; j < 8; j++) {
        size_t o4 = (((size_t)(b * CC + oc0 + j)) << 12) + 4 * n4;
        float4 h, l, v = acc[j];
        h.x = __uint_as_float(cvt_tf32(v.x)); l.x = __uint_as_float(cvt_tf32(v.x - h.x));
        h.y = __uint_as_float(cvt_tf32(v.y)); l.y = __uint_as_float(cvt_tf32(v.y - h.y));
        h.z = __uint_as_float(cvt_tf32(v.z)); l.z = __uint_as_float(cvt_tf32(v.z - h.z));
        h.w = __uint_as_float(cvt_tf32(v.w)); l.w = __uint_as_float(cvt_tf32(v.w - h.w));
        *(float4*)(zh + o4) = h;
        *(float4*)(zl + o4) = l;
    }
}

// ---------------- driver -----------------------------------------------------
extern "C" void kernel_launch(void* const* d_in, const int* in_sizes, int n_in,
                              void* d_out, int out_size)
{
    const float* x       = (const float*)d_in[0];
    const float* conv1_w = (const float*)d_in[1];
    const float* bn1_g   = (const float*)d_in[2];
    const float* bn1_b   = (const float*)d_in[3];
    const float* theta_w = (const float*)d_in[4];
    const float* theta_b = (const float*)d_in[5];
    const float* phi_w   = (const float*)d_in[6];
    const float* phi_b   = (const float*)d_in[7];
    const float* g_w     = (const float*)d_in[8];
    const float* g_b     = (const float*)d_in[9];
    const float* W_w     = (const float*)d_in[10];
    const float* W_b     = (const float*)d_in[11];
    const float* conv2_w = (const float*)d_in[12];
    const float* bn2_g   = (const float*)d_in[13];
    const float* bn2_b   = (const float*)d_in[14];
    float* out = (float*)d_out;

    float* buf = nullptr;
    cudaGetSymbolAddress((void**)&buf, g_buf);
    float* raw   = buf + OFF_RAW;
    float* x1h   = buf + OFF_X1H;
    float* x1l   = buf + OFF_X1L;
    float* th    = buf + OFF_TH;
    float* phi   = buf + OFF_PHI;
    float* gbuf  = buf + OFF_G;
    float* ybuf  = buf + OFF_Y;
    float* zh    = buf + OFF_ZH;
    float* zl    = buf + OFF_ZL;
    float* xh    = buf + OFF_XH;
    float* xl    = buf + OFF_XL;
    float* wth   = buf + OFF_WTH;
    float* wtl   = buf + OFF_WTL;
    float* scale = buf + OFF_SC;
    float* shift = buf + OFF_SH;

    cudaFuncSetAttribute(conv3x3_mma_kernel,
                         cudaFuncAttributeMaxDynamicSharedMemorySize, CONV_SMEM);

    // weight prep + input split
    wtrans_all_kernel<<<720, 256>>>(conv1_w, theta_w, phi_w, g_w, conv2_w, wth, wtl);
    split_kernel<<<1024, 256>>>((const float4*)x, (float4*)xh, (float4*)xl);

    // conv1 -> BN -> ReLU (tf32 split output)
    conv3x3_mma_kernel<<<dim3(32, 4, 1), 128, CONV_SMEM>>>(
        xh, xl, wth, wtl, nullptr, nullptr, nullptr, raw, raw, raw, 0, 0);
    bn_stats_kernel<<<64, 256>>>(raw, bn1_g, bn1_b, scale, shift);
    bn_apply_relu_split_kernel<<<1024, 256>>>(
        (const float4*)raw, scale, shift, (float4*)x1h, (float4*)x1l);

    // theta (trans,half), phi (half), g (trans,half) in one launch
    conv3x3_mma_kernel<<<dim3(32, 4, 3), 128, CONV_SMEM>>>(
        x1h, x1l, wth + 1 * WSET, wtl + 1 * WSET,
        theta_b, phi_b, g_b, th, phi, gbuf, 0b101, 0b111);

    // attention (fp16 tensor cores, Br=128)
    flash_f16_kernel<<<dim3(NN / 128, BB), 256, FLASH_SMEM>>>(
        (const __half*)th, (const __half*)phi, (const __half*)gbuf, ybuf);

    // 1x1 W conv + residual -> split z
    w1x1_res_kernel<<<128, 256>>>(ybuf, W_w, W_b, x, zh, zl);

    // conv2 -> BN -> ReLU -> out
    conv3x3_mma_kernel<<<dim3(32, 4, 1), 128, CONV_SMEM>>>(
        zh, zl, wth + 4 * WSET, wtl + 4 * WSET,
        nullptr, nullptr, nullptr, raw, raw, raw, 0, 0);
    bn_stats_kernel<<<64, 256>>>(raw, bn2_g, bn2_b, scale, shift);
    bn_apply_relu_kernel<<<1024, 256>>>((const float4*)raw, scale, shift, (float4*)out);
}

// round 8
// speedup vs baseline: 1.3154x; 1.3154x over previous
#include <cuda_runtime.h>
#include <cuda_fp16.h>
#include <math.h>
#include <stdint.h>

#define CC 64
#define HH 64
#define WWD 64
#define NN 4096
#define BB 4

// ---------------- scratch (static device memory; no allocs allowed) ----------
__device__ float g_buf[12u * 1024u * 1024u];

static const size_t OFF_RAW = 0;            // fp32 1M
static const size_t OFF_TH  = 1u << 20;     // fp32 [B,N,C]
static const size_t OFF_PHI = 2u << 20;     // fp32 [B,C,N]
static const size_t OFF_G   = 3u << 20;     // fp32 [B,N,C]
static const size_t OFF_Y   = 4u << 20;     // fp32 [B,C,N]
static const size_t OFF_X1P = 5u << 20;     // half2-packed [B,32,N] (0.5M u32)
static const size_t OFF_ZP  = OFF_X1P + (1u << 19);
static const size_t OFF_XP  = OFF_ZP + (1u << 19);
static const size_t OFF_WP  = OFF_XP + (1u << 19);   // 102400 u32
static const size_t OFF_SC  = OFF_WP + 102400;
static const size_t OFF_SH  = OFF_SC + 64;
static const size_t OFF_PT  = OFF_SH + 64;           // partials 64*4*2

// ---------------- mma helpers --------------------------------------------------
__device__ __forceinline__ void mma_tf32(float c[4], const uint32_t a[4],
                                         uint32_t b0, uint32_t b1) {
    asm volatile(
        "mma.sync.aligned.m16n8k8.row.col.f32.tf32.tf32.f32 "
        "{%0,%1,%2,%3}, {%4,%5,%6,%7}, {%8,%9}, {%0,%1,%2,%3};"
        : "+f"(c[0]), "+f"(c[1]), "+f"(c[2]), "+f"(c[3])
        : "r"(a[0]), "r"(a[1]), "r"(a[2]), "r"(a[3]), "r"(b0), "r"(b1));
}

__device__ __forceinline__ uint32_t cvt_tf32(float f) {
    uint32_t r;
    asm("cvt.rna.tf32.f32 %0, %1;" : "=r"(r) : "f"(f));
    return r;
}

__device__ __forceinline__ void mma_f16_k16(float c[4], const uint32_t a[4],
                                            uint32_t b0, uint32_t b1) {
    asm volatile(
        "mma.sync.aligned.m16n8k16.row.col.f32.f16.f16.f32 "
        "{%0,%1,%2,%3}, {%4,%5,%6,%7}, {%8,%9}, {%0,%1,%2,%3};"
        : "+f"(c[0]), "+f"(c[1]), "+f"(c[2]), "+f"(c[3])
        : "r"(a[0]), "r"(a[1]), "r"(a[2]), "r"(a[3]), "r"(b0), "r"(b1));
}

__device__ __forceinline__ void mma_f16_k8(float c[4], uint32_t a0, uint32_t a1,
                                           uint32_t b0) {
    asm volatile(
        "mma.sync.aligned.m16n8k8.row.col.f32.f16.f16.f32 "
        "{%0,%1,%2,%3}, {%4,%5}, {%6}, {%0,%1,%2,%3};"
        : "+f"(c[0]), "+f"(c[1]), "+f"(c[2]), "+f"(c[3])
        : "r"(a0), "r"(a1), "r"(b0));
}

// ---------------- weight prep: 5 sets -> [s][ch][kp=40][oc=64] half2 ----------
// k within chunk = tap*8 + icL (pairs over icL); kp = tap*4 + icp; kp 36..39 = 0
__global__ void wtrans_f16_kernel(
    const float* __restrict__ w0, const float* __restrict__ w1,
    const float* __restrict__ w2, const float* __restrict__ w3,
    const float* __restrict__ w4, uint32_t* __restrict__ wp)
{
    int i = blockIdx.x * 256 + threadIdx.x;
    if (i >= 5 * 8 * 40 * 64) return;
    int s  = i / 20480;
    int r  = i - s * 20480;
    int ch = r / 2560;
    int r2 = r - ch * 2560;
    int kp = r2 >> 6;
    int oc = r2 & 63;
    uint32_t outv = 0;
    if (kp < 36) {
        const float* w = (s == 0) ? w0 : (s == 1) ? w1 : (s == 2) ? w2 : (s == 3) ? w3 : w4;
        int tap = kp >> 2;
        int icp = kp & 3;
        int ic  = ch * 8 + icp * 2;
        float v0 = w[oc * 576 + ic * 9 + tap];
        float v1 = w[oc * 576 + (ic + 1) * 9 + tap];
        __half2 h = __floats2half2_rn(v0, v1);
        outv = *(uint32_t*)&h;
    }
    wp[i] = outv;
}

// ---------------- pack fp32 [B,C,N] -> half2 [B,C/2,N] -------------------------
__global__ void pack_x_kernel(const float* __restrict__ in, uint32_t* __restrict__ outp)
{
    int i = blockIdx.x * 256 + threadIdx.x;          // 524288
    int b  = i >> 17;
    int cp = (i >> 12) & 31;
    int n  = i & 4095;
    size_t base = (((size_t)(b * CC + 2 * cp)) << 12) + n;
    __half2 h = __floats2half2_rn(in[base], in[base + 4096]);
    outp[i] = *(uint32_t*)&h;
}

// ---------------- 3x3 conv, fp16 tensor cores ---------------------------------
// Block: 64 oc x 128 px (2 rows), 4 warps each 64m x 32n.
// inP: half2 [B,32,4096]. wp: [set][ch][kp=40][64] half2 (set via blockIdx.z).
__global__ void __launch_bounds__(128) conv3x3_f16_kernel(
    const uint32_t* __restrict__ inP, const uint32_t* __restrict__ wp,
    const float* __restrict__ bias0, const float* __restrict__ bias1,
    const float* __restrict__ bias2,
    float* __restrict__ out0, float* __restrict__ out1, float* __restrict__ out2,
    int trans_mask)
{
    extern __shared__ __align__(16) uint32_t smc[];
    uint32_t* Aw = smc;            // [40][72] = 2880 u32
    uint32_t* Is = smc + 2880;     // [icp=4][r=4][74] = 1184 u32 (icp stride 296)

    int s = blockIdx.z;
    const float* bias = (s == 0) ? bias0 : (s == 1) ? bias1 : bias2;
    float* out = (s == 0) ? out0 : (s == 1) ? out1 : out2;
    int trans = (trans_mask >> s) & 1;
    const uint32_t* wps = wp + (size_t)s * 20480;

    int b   = blockIdx.y;
    int y0  = blockIdx.x * 2;
    int tid = threadIdx.x;
    int w    = tid >> 5;
    int lane = tid & 31;
    int gid  = lane >> 2;
    int tig  = lane & 3;
    int wy = w >> 1;               // output row (0/1) within pair
    int wx = (w & 1) * 32;         // x offset

    float c[4][4][4];
#pragma unroll
    for (int mt = 0; mt < 4; mt++)
#pragma unroll
        for (int nt = 0; nt < 4; nt++)
#pragma unroll
            for (int r = 0; r < 4; r++) c[mt][nt][r] = 0.f;

    for (int ch = 0; ch < 8; ch++) {
        __syncthreads();
        // weights: 40 kp x 64 oc
        for (int i = tid; i < 2560; i += 128) {
            int kp = i >> 6, oc = i & 63;
            Aw[kp * 72 + oc] = wps[ch * 2560 + i];
        }
        // input: 4 icp x 4 rows x 66 cols (half2; zero border)
        for (int i = tid; i < 1056; i += 128) {
            int icp = i / 264;
            int rem = i - icp * 264;
            int r   = rem / 66;
            int col = rem - r * 66;
            int gy = y0 + r - 1;
            int gx = col - 1;
            uint32_t v = 0;
            if (gy >= 0 && gy < HH && gx >= 0 && gx < WWD)
                v = inP[(((size_t)(b * 32 + ch * 4 + icp)) << 12) + (gy << 6) + gx];
            Is[icp * 296 + r * 74 + col] = v;
        }
        __syncthreads();

        // 4 k16 steps: taps (2kk, 2kk+1)
#pragma unroll
        for (int kk = 0; kk < 4; kk++) {
            const int t0 = 2 * kk, t1 = 2 * kk + 1;
            const int ky0 = t0 / 3, kx0 = t0 % 3;
            const int ky1 = t1 / 3, kx1 = t1 % 3;
            uint32_t bf0[4], bf1[4];
#pragma unroll
            for (int nt = 0; nt < 4; nt++) {
                int col = wx + 8 * nt + gid;
                bf0[nt] = Is[tig * 296 + (wy + ky0) * 74 + col + kx0];
                bf1[nt] = Is[tig * 296 + (wy + ky1) * 74 + col + kx1];
            }
#pragma unroll
            for (int mt = 0; mt < 4; mt++) {
                int colA = mt * 16 + gid;
                uint32_t a[4];
                a[0] = Aw[(8 * kk + tig) * 72 + colA];
                a[1] = Aw[(8 * kk + tig) * 72 + colA + 8];
                a[2] = Aw[(8 * kk + tig + 4) * 72 + colA];
                a[3] = Aw[(8 * kk + tig + 4) * 72 + colA + 8];
#pragma unroll
                for (int nt = 0; nt < 4; nt++)
                    mma_f16_k16(c[mt][nt], a, bf0[nt], bf1[nt]);
            }
        }
        // k8 step: tap 8 (ky=2, kx=2), kp = 32+tig
        {
            uint32_t bf[4];
#pragma unroll
            for (int nt = 0; nt < 4; nt++)
                bf[nt] = Is[tig * 296 + (wy + 2) * 74 + wx + 8 * nt + gid + 2];
#pragma unroll
            for (int mt = 0; mt < 4; mt++) {
                int colA = mt * 16 + gid;
                uint32_t a0 = Aw[(32 + tig) * 72 + colA];
                uint32_t a1 = Aw[(32 + tig) * 72 + colA + 8];
#pragma unroll
                for (int nt = 0; nt < 4; nt++)
                    mma_f16_k8(c[mt][nt], a0, a1, bf[nt]);
            }
        }
    }

    // ---- epilogue: bias, stage [oc][128] pitch 130 fp32, coalesced write ----
    __syncthreads();
    float* Os = (float*)smc;       // 64*130 = 8320 floats
    float bv0[4], bv1[4];
#pragma unroll
    for (int mt = 0; mt < 4; mt++) {
        bv0[mt] = bias ? bias[mt * 16 + gid] : 0.f;
        bv1[mt] = bias ? bias[mt * 16 + gid + 8] : 0.f;
    }
#pragma unroll
    for (int mt = 0; mt < 4; mt++)
#pragma unroll
        for (int nt = 0; nt < 4; nt++) {
            int n = wx + wy * 64 + nt * 8 + 2 * tig;
            float2 v0, v1;
            v0.x = c[mt][nt][0] + bv0[mt];
            v0.y = c[mt][nt][1] + bv0[mt];
            v1.x = c[mt][nt][2] + bv1[mt];
            v1.y = c[mt][nt][3] + bv1[mt];
            *(float2*)(Os + (mt * 16 + gid) * 130 + n) = v0;
            *(float2*)(Os + (mt * 16 + gid + 8) * 130 + n) = v1;
        }
    __syncthreads();
    int n0 = blockIdx.x * 128;
    if (!trans) {
        for (int i = tid; i < 8192; i += 128) {
            int oc = i >> 7, nl = i & 127;
            out[(((size_t)(b * CC + oc)) << 12) + n0 + nl] = Os[oc * 130 + nl];
        }
    } else {
        for (int i = tid; i < 8192; i += 128) {
            int nl = i >> 6, oc = i & 63;
            out[((size_t)b * NN + n0 + nl) * CC + oc] = Os[oc * 130 + nl];
        }
    }
}
#define CONV_SMEM (33280)

// ---------------- BN stats: 2-stage -------------------------------------------
__global__ void bn_stats_part_kernel(const float* __restrict__ in,
                                     float* __restrict__ part)
{
    int c = blockIdx.x, b = blockIdx.y;
    int tid = threadIdx.x;
    const float4* p4 = (const float4*)(in + (((size_t)(b * CC + c)) << 12));
    float s = 0.f, s2 = 0.f;
#pragma unroll
    for (int i = tid; i < 1024; i += 256) {
        float4 v = p4[i];
        s  += v.x + v.y + v.z + v.w;
        s2 += v.x * v.x + v.y * v.y + v.z * v.z + v.w * v.w;
    }
    __shared__ float sh[256], sh2[256];
    sh[tid] = s; sh2[tid] = s2;
    __syncthreads();
    for (int o = 128; o > 0; o >>= 1) {
        if (tid < o) { sh[tid] += sh[tid + o]; sh2[tid] += sh2[tid + o]; }
        __syncthreads();
    }
    if (tid == 0) {
        part[(c * BB + b) * 2]     = sh[0];
        part[(c * BB + b) * 2 + 1] = sh2[0];
    }
}

__global__ void bn_final_kernel(const float* __restrict__ part,
                                const float* __restrict__ gamma,
                                const float* __restrict__ beta,
                                float* __restrict__ scale, float* __restrict__ shift)
{
    int c = threadIdx.x;
    float s = 0.f, s2 = 0.f;
#pragma unroll
    for (int b = 0; b < BB; b++) {
        s  += part[(c * BB + b) * 2];
        s2 += part[(c * BB + b) * 2 + 1];
    }
    const float inv = 1.f / (float)(BB * NN);
    float mean = s * inv;
    float var  = s2 * inv - mean * mean;
    float r    = rsqrtf(var + 1e-5f);
    float sc   = gamma[c] * r;
    scale[c] = sc;
    shift[c] = beta[c] - mean * sc;
}

__global__ void bn_apply_relu_kernel(const float4* __restrict__ in,
                                     const float* __restrict__ scale,
                                     const float* __restrict__ shift,
                                     float4* __restrict__ out)
{
    int i = blockIdx.x * 256 + threadIdx.x;
    int c = (i >> 10) & 63;
    float sc = scale[c], sf = shift[c];
    float4 v = in[i];
    v.x = fmaxf(fmaf(v.x, sc, sf), 0.f);
    v.y = fmaxf(fmaf(v.y, sc, sf), 0.f);
    v.z = fmaxf(fmaf(v.z, sc, sf), 0.f);
    v.w = fmaxf(fmaf(v.w, sc, sf), 0.f);
    out[i] = v;
}

// BN + ReLU -> half2 packed [B,32,N]
__global__ void bn_apply_relu_pack_kernel(const float* __restrict__ in,
                                          const float* __restrict__ scale,
                                          const float* __restrict__ shift,
                                          uint32_t* __restrict__ outp)
{
    int i = blockIdx.x * 256 + threadIdx.x;          // 524288
    int b  = i >> 17;
    int cp = (i >> 12) & 31;
    int n  = i & 4095;
    size_t base = (((size_t)(b * CC + 2 * cp)) << 12) + n;
    float v0 = fmaxf(fmaf(in[base],        scale[2 * cp],     shift[2 * cp]),     0.f);
    float v1 = fmaxf(fmaf(in[base + 4096], scale[2 * cp + 1], shift[2 * cp + 1]), 0.f);
    __half2 h = __floats2half2_rn(v0, v1);
    outp[i] = *(uint32_t*)&h;
}

// ---------------- flash attention (tf32, proven R4 version) --------------------
#define KP 72
__global__ void __launch_bounds__(128) flash_tf32_kernel(
    const float* __restrict__ Qt, const float* __restrict__ K,
    const float* __restrict__ Gt, float* __restrict__ Y)
{
    extern __shared__ __align__(16) float sm[];
    float* Ks = sm;
    float* Gs = sm + 64 * KP;
    float* Ps = sm + 128 * KP;

    int b   = blockIdx.y;
    int n0  = blockIdx.x * 64;
    int tid = threadIdx.x;
    int w    = tid >> 5;
    int lane = tid & 31;
    int gid  = lane >> 2;
    int tig  = lane & 3;
    float* Pw = Ps + w * 16 * KP;

    uint32_t aq[8][4];
    {
        const float* qb = Qt + ((size_t)b * NN + n0 + w * 16) * CC;
#pragma unroll
        for (int k = 0; k < 8; k++) {
            aq[k][0] = cvt_tf32(qb[(size_t)gid * CC + 8 * k + tig]);
            aq[k][1] = cvt_tf32(qb[(size_t)(gid + 8) * CC + 8 * k + tig]);
            aq[k][2] = cvt_tf32(qb[(size_t)gid * CC + 8 * k + 4 + tig]);
            aq[k][3] = cvt_tf32(qb[(size_t)(gid + 8) * CC + 8 * k + 4 + tig]);
        }
    }

    float o[8][4];
#pragma unroll
    for (int nt = 0; nt < 8; nt++)
#pragma unroll
        for (int r = 0; r < 4; r++) o[nt][r] = 0.f;
    float rm0 = -1e30f, rm1 = -1e30f, rl0 = 0.f, rl1 = 0.f;

    for (int j0 = 0; j0 < NN; j0 += 64) {
        __syncthreads();
        for (int idx = tid; idx < 1024; idx += 128) {
            int row = idx >> 4;
            int c4  = (idx & 15) << 2;
            float4 kv = *(const float4*)(K + (((size_t)(b * CC + row)) << 12) + j0 + c4);
            uint4 kb;
            kb.x = cvt_tf32(kv.x); kb.y = cvt_tf32(kv.y);
            kb.z = cvt_tf32(kv.z); kb.w = cvt_tf32(kv.w);
            *(uint4*)(Ks + row * KP + c4) = kb;
            float4 gv = *(const float4*)(Gt + ((size_t)b * NN + j0 + row) * CC + c4);
            uint4 gb;
            gb.x = cvt_tf32(gv.x); gb.y = cvt_tf32(gv.y);
            gb.z = cvt_tf32(gv.z); gb.w = cvt_tf32(gv.w);
            *(uint4*)(Gs + row * KP + c4) = gb;
        }
        __syncthreads();

        float s[8][4];
#pragma unroll
        for (int nt = 0; nt < 8; nt++)
#pragma unroll
            for (int r = 0; r < 4; r++) s[nt][r] = 0.f;

#pragma unroll
        for (int kk = 0; kk < 8; kk++) {
            const float* kr0 = Ks + (8 * kk + tig) * KP + gid;
            const float* kr1 = Ks + (8 * kk + tig + 4) * KP + gid;
#pragma unroll
            for (int nt = 0; nt < 8; nt++) {
                uint32_t b0 = __float_as_uint(kr0[8 * nt]);
                uint32_t b1 = __float_as_uint(kr1[8 * nt]);
                mma_tf32(s[nt], aq[kk], b0, b1);
            }
        }

        float mx0 = -1e30f, mx1 = -1e30f;
#pragma unroll
        for (int nt = 0; nt < 8; nt++) {
            mx0 = fmaxf(mx0, fmaxf(s[nt][0], s[nt][1]));
            mx1 = fmaxf(mx1, fmaxf(s[nt][2], s[nt][3]));
        }
        mx0 = fmaxf(mx0, __shfl_xor_sync(0xffffffffu, mx0, 1));
        mx0 = fmaxf(mx0, __shfl_xor_sync(0xffffffffu, mx0, 2));
        mx1 = fmaxf(mx1, __shfl_xor_sync(0xffffffffu, mx1, 1));
        mx1 = fmaxf(mx1, __shfl_xor_sync(0xffffffffu, mx1, 2));

        float mn0 = fmaxf(rm0, mx0), mn1 = fmaxf(rm1, mx1);
        float al0 = __expf(rm0 - mn0), al1 = __expf(rm1 - mn1);
        rm0 = mn0; rm1 = mn1;

        float rs0 = 0.f, rs1 = 0.f;
#pragma unroll
        for (int nt = 0; nt < 8; nt++) {
            float p0 = __expf(s[nt][0] - mn0);
            float p1 = __expf(s[nt][1] - mn0);
            float p2 = __expf(s[nt][2] - mn1);
            float p3 = __expf(s[nt][3] - mn1);
            rs0 += p0 + p1; rs1 += p2 + p3;
            uint2 v01; v01.x = cvt_tf32(p0); v01.y = cvt_tf32(p1);
            uint2 v23; v23.x = cvt_tf32(p2); v23.y = cvt_tf32(p3);
            *(uint2*)(Pw + gid * KP + 8 * nt + 2 * tig) = v01;
            *(uint2*)(Pw + (gid + 8) * KP + 8 * nt + 2 * tig) = v23;
        }
        rs0 += __shfl_xor_sync(0xffffffffu, rs0, 1);
        rs0 += __shfl_xor_sync(0xffffffffu, rs0, 2);
        rs1 += __shfl_xor_sync(0xffffffffu, rs1, 1);
        rs1 += __shfl_xor_sync(0xffffffffu, rs1, 2);
        rl0 = rl0 * al0 + rs0;
        rl1 = rl1 * al1 + rs1;

#pragma unroll
        for (int nt = 0; nt < 8; nt++) {
            o[nt][0] *= al0; o[nt][1] *= al0;
            o[nt][2] *= al1; o[nt][3] *= al1;
        }
        __syncwarp();

#pragma unroll
        for (int kk = 0; kk < 8; kk++) {
            uint32_t pa[4];
            pa[0] = __float_as_uint(Pw[gid * KP + 8 * kk + tig]);
            pa[1] = __float_as_uint(Pw[(gid + 8) * KP + 8 * kk + tig]);
            pa[2] = __float_as_uint(Pw[gid * KP + 8 * kk + 4 + tig]);
            pa[3] = __float_as_uint(Pw[(gid + 8) * KP + 8 * kk + 4 + tig]);
            const float* gr0 = Gs + (8 * kk + tig) * KP + gid;
            const float* gr1 = Gs + (8 * kk + tig + 4) * KP + gid;
#pragma unroll
            for (int nt = 0; nt < 8; nt++) {
                uint32_t b0 = __float_as_uint(gr0[8 * nt]);
                uint32_t b1 = __float_as_uint(gr1[8 * nt]);
                mma_tf32(o[nt], pa, b0, b1);
            }
        }
    }

    __syncthreads();
    float li0 = 1.f / rl0, li1 = 1.f / rl1;
    float* Os = Ks;
#pragma unroll
    for (int nt = 0; nt < 8; nt++) {
        float2 v0; v0.x = o[nt][0] * li0; v0.y = o[nt][1] * li0;
        float2 v1; v1.x = o[nt][2] * li1; v1.y = o[nt][3] * li1;
        *(float2*)(Os + (w * 16 + gid) * KP + 8 * nt + 2 * tig) = v0;
        *(float2*)(Os + (w * 16 + gid + 8) * KP + 8 * nt + 2 * tig) = v1;
    }
    __syncthreads();
    for (int i = tid; i < 4096; i += 128) {
        int c = i >> 6, q = i & 63;
        Y[(((size_t)(b * CC + c)) << 12) + n0 + q] = Os[q * KP + c];
    }
}
#define FLASH_SMEM ((192 * KP) * (int)sizeof(float))

// ---------------- 1x1 conv + bias + residual -> half2 packed ------------------
__global__ void __launch_bounds__(256) w1x1_res_pack_kernel(
    const float* __restrict__ y, const float* __restrict__ Ww,
    const float* __restrict__ Wb, const float* __restrict__ x,
    uint32_t* __restrict__ zp)
{
    __shared__ float Ws[64 * 65];
    int tid = threadIdx.x;
    for (int i = tid; i < 4096; i += 256) {
        int oc = i >> 6, ic = i & 63;
        Ws[ic * 65 + oc] = Ww[i];
    }
    __syncthreads();

    int og = tid & 3;
    int nl = tid >> 2;
    int gpos = blockIdx.x * 64 + nl;
    int b = gpos >> 12, n = gpos & 4095;
    int oc0 = og * 16;

    float acc[16];
#pragma unroll
    for (int j = 0; j < 16; j++)
        acc[j] = Wb[oc0 + j] + x[(((size_t)(b * CC + oc0 + j)) << 12) + n];

    for (int ic = 0; ic < 64; ic++) {
        float v = y[(((size_t)(b * CC + ic)) << 12) + n];
#pragma unroll
        for (int j = 0; j < 16; j++)
            acc[j] = fmaf(v, Ws[ic * 65 + oc0 + j], acc[j]);
    }
#pragma unroll
    for (int j = 0; j < 16; j += 2) {
        __half2 h = __floats2half2_rn(acc[j], acc[j + 1]);
        zp[(((size_t)(b * 32 + (oc0 >> 1) + (j >> 1))) << 12) + n] = *(uint32_t*)&h;
    }
}

// ---------------- driver -----------------------------------------------------
extern "C" void kernel_launch(void* const* d_in, const int* in_sizes, int n_in,
                              void* d_out, int out_size)
{
    const float* x       = (const float*)d_in[0];
    const float* conv1_w = (const float*)d_in[1];
    const float* bn1_g   = (const float*)d_in[2];
    const float* bn1_b   = (const float*)d_in[3];
    const float* theta_w = (const float*)d_in[4];
    const float* theta_b = (const float*)d_in[5];
    const float* phi_w   = (const float*)d_in[6];
    const float* phi_b   = (const float*)d_in[7];
    const float* g_w     = (const float*)d_in[8];
    const float* g_b     = (const float*)d_in[9];
    const float* W_w     = (const float*)d_in[10];
    const float* W_b     = (const float*)d_in[11];
    const float* conv2_w = (const float*)d_in[12];
    const float* bn2_g   = (const float*)d_in[13];
    const float* bn2_b   = (const float*)d_in[14];
    float* out = (float*)d_out;

    float* buf = nullptr;
    cudaGetSymbolAddress((void**)&buf, g_buf);
    float*    raw   = buf + OFF_RAW;
    float*    th    = buf + OFF_TH;
    float*    phi   = buf + OFF_PHI;
    float*    gbuf  = buf + OFF_G;
    float*    ybuf  = buf + OFF_Y;
    uint32_t* x1p   = (uint32_t*)(buf + OFF_X1P);
    uint32_t* zp    = (uint32_t*)(buf + OFF_ZP);
    uint32_t* xp    = (uint32_t*)(buf + OFF_XP);
    uint32_t* wpbuf = (uint32_t*)(buf + OFF_WP);
    float*    scale = buf + OFF_SC;
    float*    shift = buf + OFF_SH;
    float*    part  = buf + OFF_PT;

    cudaFuncSetAttribute(flash_tf32_kernel,
                         cudaFuncAttributeMaxDynamicSharedMemorySize, FLASH_SMEM);
    cudaFuncSetAttribute(conv3x3_f16_kernel,
                         cudaFuncAttributeMaxDynamicSharedMemorySize, CONV_SMEM);

    // weight prep + input pack
    wtrans_f16_kernel<<<400, 256>>>(conv1_w, theta_w, phi_w, g_w, conv2_w, wpbuf);
    pack_x_kernel<<<2048, 256>>>(x, xp);

    // conv1 -> BN -> ReLU (packed output)
    conv3x3_f16_kernel<<<dim3(32, 4, 1), 128, CONV_SMEM>>>(
        xp, wpbuf, nullptr, nullptr, nullptr, raw, raw, raw, 0);
    bn_stats_part_kernel<<<dim3(64, BB), 256>>>(raw, part);
    bn_final_kernel<<<1, 64>>>(part, bn1_g, bn1_b, scale, shift);
    bn_apply_relu_pack_kernel<<<2048, 256>>>(raw, scale, shift, x1p);

    // theta (trans), phi, g (trans) in one launch: sets 1,2,3
    conv3x3_f16_kernel<<<dim3(32, 4, 3), 128, CONV_SMEM>>>(
        x1p, wpbuf + 20480, theta_b, phi_b, g_b, th, phi, gbuf, 0b101);

    // attention (tf32, proven)
    flash_tf32_kernel<<<dim3(NN / 64, BB), 128, FLASH_SMEM>>>(th, phi, gbuf, ybuf);

    // 1x1 W conv + residual -> packed z
    w1x1_res_pack_kernel<<<256, 256>>>(ybuf, W_w, W_b, x, zp);

    // conv2 -> BN -> ReLU -> out
    conv3x3_f16_kernel<<<dim3(32, 4, 1), 128, CONV_SMEM>>>(
        zp, wpbuf + 4 * 20480, nullptr, nullptr, nullptr, raw, raw, raw, 0);
    bn_stats_part_kernel<<<dim3(64, BB), 256>>>(raw, part);
    bn_final_kernel<<<1, 64>>>(part, bn2_g, bn2_b, scale, shift);
    bn_apply_relu_kernel<<<1024, 256>>>((const float4*)raw, scale, shift, (float4*)out);
}

// round 10
// speedup vs baseline: 1.6931x; 1.2871x over previous
#include <cuda_runtime.h>
#include <cuda_fp16.h>
#include <math.h>
#include <stdint.h>

#define CC 64
#define HH 64
#define WWD 64
#define NN 4096
#define BB 4

// ---------------- scratch (static device memory; no allocs allowed) ----------
__device__ float g_buf[8u * 1024u * 1024u];

static const size_t OFF_RAW = 0;                       // fp32 1M
static const size_t OFF_Y   = 1u << 20;                // fp32 [B,C,N]
static const size_t OFF_TH2 = 2u << 20;                // u32 [B,N,32] c-pairs
static const size_t OFF_PH2 = OFF_TH2 + (1u << 19);    // u32 [B,32,N] c-pairs
static const size_t OFF_GP2 = OFF_PH2 + (1u << 19);    // u32 [B,N/2,64] n-pairs
static const size_t OFF_X1P = OFF_GP2 + (1u << 19);    // u32 [B,32,N]
static const size_t OFF_ZP  = OFF_X1P + (1u << 19);
static const size_t OFF_XP  = OFF_ZP + (1u << 19);
static const size_t OFF_WP  = OFF_XP + (1u << 19);     // 102400 u32
static const size_t OFF_SC  = OFF_WP + 102400;
static const size_t OFF_SH  = OFF_SC + 64;
static const size_t OFF_PT  = OFF_SH + 64;

// ---------------- mma helpers --------------------------------------------------
__device__ __forceinline__ void mma_f16_k16(float c[4], const uint32_t a[4],
                                            uint32_t b0, uint32_t b1) {
    asm volatile(
        "mma.sync.aligned.m16n8k16.row.col.f32.f16.f16.f32 "
        "{%0,%1,%2,%3}, {%4,%5,%6,%7}, {%8,%9}, {%0,%1,%2,%3};"
        : "+f"(c[0]), "+f"(c[1]), "+f"(c[2]), "+f"(c[3])
        : "r"(a[0]), "r"(a[1]), "r"(a[2]), "r"(a[3]), "r"(b0), "r"(b1));
}

__device__ __forceinline__ void mma_f16_k8(float c[4], uint32_t a0, uint32_t a1,
                                           uint32_t b0) {
    asm volatile(
        "mma.sync.aligned.m16n8k8.row.col.f32.f16.f16.f32 "
        "{%0,%1,%2,%3}, {%4,%5}, {%6}, {%0,%1,%2,%3};"
        : "+f"(c[0]), "+f"(c[1]), "+f"(c[2]), "+f"(c[3])
        : "r"(a0), "r"(a1), "r"(b0));
}

// ---------------- weight prep: 5 sets -> [s][ch][kp=40][oc=64] half2 ----------
__global__ void wtrans_f16_kernel(
    const float* __restrict__ w0, const float* __restrict__ w1,
    const float* __restrict__ w2, const float* __restrict__ w3,
    const float* __restrict__ w4, uint32_t* __restrict__ wp)
{
    int i = blockIdx.x * 256 + threadIdx.x;
    if (i >= 5 * 8 * 40 * 64) return;
    int s  = i / 20480;
    int r  = i - s * 20480;
    int ch = r / 2560;
    int r2 = r - ch * 2560;
    int kp = r2 >> 6;
    int oc = r2 & 63;
    uint32_t outv = 0;
    if (kp < 36) {
        const float* w = (s == 0) ? w0 : (s == 1) ? w1 : (s == 2) ? w2 : (s == 3) ? w3 : w4;
        int tap = kp >> 2;
        int icp = kp & 3;
        int ic  = ch * 8 + icp * 2;
        float v0 = w[oc * 576 + ic * 9 + tap];
        float v1 = w[oc * 576 + (ic + 1) * 9 + tap];
        __half2 h = __floats2half2_rn(v0, v1);
        outv = *(uint32_t*)&h;
    }
    wp[i] = outv;
}

// ---------------- pack fp32 [B,C,N] -> half2 [B,C/2,N] -------------------------
__global__ void pack_x_kernel(const float* __restrict__ in, uint32_t* __restrict__ outp)
{
    int i = blockIdx.x * 256 + threadIdx.x;
    int b  = i >> 17;
    int cp = (i >> 12) & 31;
    int n  = i & 4095;
    size_t base = (((size_t)(b * CC + 2 * cp)) << 12) + n;
    __half2 h = __floats2half2_rn(in[base], in[base + 4096]);
    outp[i] = *(uint32_t*)&h;
}

// ---------------- 3x3 conv, fp16 tensor cores ---------------------------------
// Block: 64 oc x 128 px (2 rows), 4 warps each 64m x 32n.
// Output modes (per s, 8 bits in `modes`):
//  0: fp32 [B,C,N]
//  1: u32 c-pairs [B,N,32]   (theta -> Q)
//  2: u32 c-pairs [B,32,N]   (phi   -> K)
//  3: u32 n-pairs [B,N/2,64] (g     -> G)
__global__ void __launch_bounds__(128) conv3x3_f16_kernel(
    const uint32_t* __restrict__ inP, const uint32_t* __restrict__ wp,
    const float* __restrict__ bias0, const float* __restrict__ bias1,
    const float* __restrict__ bias2,
    void* __restrict__ out0, void* __restrict__ out1, void* __restrict__ out2,
    int modes)
{
    extern __shared__ __align__(16) uint32_t smc[];
    uint32_t* Aw = smc;            // [40][72]
    uint32_t* Is = smc + 2880;     // [icp=4][r=4][74] icp stride 296

    int s = blockIdx.z;
    const float* bias = (s == 0) ? bias0 : (s == 1) ? bias1 : bias2;
    void* out = (s == 0) ? out0 : (s == 1) ? out1 : out2;
    int mode = (modes >> (8 * s)) & 0xff;
    const uint32_t* wps = wp + (size_t)s * 20480;

    int b   = blockIdx.y;
    int y0  = blockIdx.x * 2;
    int tid = threadIdx.x;
    int w    = tid >> 5;
    int lane = tid & 31;
    int gid  = lane >> 2;
    int tig  = lane & 3;
    int wy = w >> 1;
    int wx = (w & 1) * 32;

    float c[4][4][4];
#pragma unroll
    for (int mt = 0; mt < 4; mt++)
#pragma unroll
        for (int nt = 0; nt < 4; nt++)
#pragma unroll
            for (int r = 0; r < 4; r++) c[mt][nt][r] = 0.f;

    for (int ch = 0; ch < 8; ch++) {
        __syncthreads();
        for (int i = tid; i < 2560; i += 128) {
            int kp = i >> 6, oc = i & 63;
            Aw[kp * 72 + oc] = wps[ch * 2560 + i];
        }
        for (int i = tid; i < 1056; i += 128) {
            int icp = i / 264;
            int rem = i - icp * 264;
            int r   = rem / 66;
            int col = rem - r * 66;
            int gy = y0 + r - 1;
            int gx = col - 1;
            uint32_t v = 0;
            if (gy >= 0 && gy < HH && gx >= 0 && gx < WWD)
                v = inP[(((size_t)(b * 32 + ch * 4 + icp)) << 12) + (gy << 6) + gx];
            Is[icp * 296 + r * 74 + col] = v;
        }
        __syncthreads();

#pragma unroll
        for (int kk = 0; kk < 4; kk++) {
            const int t0 = 2 * kk, t1 = 2 * kk + 1;
            const int ky0 = t0 / 3, kx0 = t0 % 3;
            const int ky1 = t1 / 3, kx1 = t1 % 3;
            uint32_t bf0[4], bf1[4];
#pragma unroll
            for (int nt = 0; nt < 4; nt++) {
                int col = wx + 8 * nt + gid;
                bf0[nt] = Is[tig * 296 + (wy + ky0) * 74 + col + kx0];
                bf1[nt] = Is[tig * 296 + (wy + ky1) * 74 + col + kx1];
            }
#pragma unroll
            for (int mt = 0; mt < 4; mt++) {
                int colA = mt * 16 + gid;
                uint32_t a[4];
                a[0] = Aw[(8 * kk + tig) * 72 + colA];
                a[1] = Aw[(8 * kk + tig) * 72 + colA + 8];
                a[2] = Aw[(8 * kk + tig + 4) * 72 + colA];
                a[3] = Aw[(8 * kk + tig + 4) * 72 + colA + 8];
#pragma unroll
                for (int nt = 0; nt < 4; nt++)
                    mma_f16_k16(c[mt][nt], a, bf0[nt], bf1[nt]);
            }
        }
        {
            uint32_t bf[4];
#pragma unroll
            for (int nt = 0; nt < 4; nt++)
                bf[nt] = Is[tig * 296 + (wy + 2) * 74 + wx + 8 * nt + gid + 2];
#pragma unroll
            for (int mt = 0; mt < 4; mt++) {
                int colA = mt * 16 + gid;
                uint32_t a0 = Aw[(32 + tig) * 72 + colA];
                uint32_t a1 = Aw[(32 + tig) * 72 + colA + 8];
#pragma unroll
                for (int nt = 0; nt < 4; nt++)
                    mma_f16_k8(c[mt][nt], a0, a1, bf[nt]);
            }
        }
    }

    // ---- epilogue: bias, stage [oc][128] pitch 130 fp32 ----
    __syncthreads();
    float* Os = (float*)smc;
    float bv0[4], bv1[4];
#pragma unroll
    for (int mt = 0; mt < 4; mt++) {
        bv0[mt] = bias ? bias[mt * 16 + gid] : 0.f;
        bv1[mt] = bias ? bias[mt * 16 + gid + 8] : 0.f;
    }
#pragma unroll
    for (int mt = 0; mt < 4; mt++)
#pragma unroll
        for (int nt = 0; nt < 4; nt++) {
            int n = wx + wy * 64 + nt * 8 + 2 * tig;
            float2 v0, v1;
            v0.x = c[mt][nt][0] + bv0[mt];
            v0.y = c[mt][nt][1] + bv0[mt];
            v1.x = c[mt][nt][2] + bv1[mt];
            v1.y = c[mt][nt][3] + bv1[mt];
            *(float2*)(Os + (mt * 16 + gid) * 130 + n) = v0;
            *(float2*)(Os + (mt * 16 + gid + 8) * 130 + n) = v1;
        }
    __syncthreads();
    int n0 = blockIdx.x * 128;
    if (mode == 0) {
        float* of = (float*)out;
        for (int i = tid; i < 8192; i += 128) {
            int oc = i >> 7, nl = i & 127;
            of[(((size_t)(b * CC + oc)) << 12) + n0 + nl] = Os[oc * 130 + nl];
        }
    } else if (mode == 1) {        // theta: u32 [B,N,32]
        uint32_t* ou = (uint32_t*)out;
        for (int i = tid; i < 4096; i += 128) {
            int nl = i >> 5, ocp = i & 31;
            __half2 h = __floats2half2_rn(Os[2 * ocp * 130 + nl],
                                          Os[(2 * ocp + 1) * 130 + nl]);
            ou[((size_t)(b * NN + n0 + nl)) * 32 + ocp] = *(uint32_t*)&h;
        }
    } else if (mode == 2) {        // phi: u32 [B,32,N]
        uint32_t* ou = (uint32_t*)out;
        for (int i = tid; i < 4096; i += 128) {
            int cp = i >> 7, nl = i & 127;
            __half2 h = __floats2half2_rn(Os[2 * cp * 130 + nl],
                                          Os[(2 * cp + 1) * 130 + nl]);
            ou[(((size_t)(b * 32 + cp)) << 12) + n0 + nl] = *(uint32_t*)&h;
        }
    } else {                       // g: u32 [B,N/2,64]
        uint32_t* ou = (uint32_t*)out;
        for (int i = tid; i < 4096; i += 128) {
            int np = i >> 6, oc = i & 63;
            __half2 h = __floats2half2_rn(Os[oc * 130 + 2 * np],
                                          Os[oc * 130 + 2 * np + 1]);
            ou[((size_t)b * 2048 + (n0 >> 1) + np) * 64 + oc] = *(uint32_t*)&h;
        }
    }
}
#define CONV_SMEM (33280)

// ---------------- BN stats: 2-stage -------------------------------------------
__global__ void bn_stats_part_kernel(const float* __restrict__ in,
                                     float* __restrict__ part)
{
    int c = blockIdx.x, b = blockIdx.y;
    int tid = threadIdx.x;
    const float4* p4 = (const float4*)(in + (((size_t)(b * CC + c)) << 12));
    float s = 0.f, s2 = 0.f;
#pragma unroll
    for (int i = tid; i < 1024; i += 256) {
        float4 v = p4[i];
        s  += v.x + v.y + v.z + v.w;
        s2 += v.x * v.x + v.y * v.y + v.z * v.z + v.w * v.w;
    }
    __shared__ float sh[256], sh2[256];
    sh[tid] = s; sh2[tid] = s2;
    __syncthreads();
    for (int o = 128; o > 0; o >>= 1) {
        if (tid < o) { sh[tid] += sh[tid + o]; sh2[tid] += sh2[tid + o]; }
        __syncthreads();
    }
    if (tid == 0) {
        part[(c * BB + b) * 2]     = sh[0];
        part[(c * BB + b) * 2 + 1] = sh2[0];
    }
}

__global__ void bn_final_kernel(const float* __restrict__ part,
                                const float* __restrict__ gamma,
                                const float* __restrict__ beta,
                                float* __restrict__ scale, float* __restrict__ shift)
{
    int c = threadIdx.x;
    float s = 0.f, s2 = 0.f;
#pragma unroll
    for (int b = 0; b < BB; b++) {
        s  += part[(c * BB + b) * 2];
        s2 += part[(c * BB + b) * 2 + 1];
    }
    const float inv = 1.f / (float)(BB * NN);
    float mean = s * inv;
    float var  = s2 * inv - mean * mean;
    float r    = rsqrtf(var + 1e-5f);
    float sc   = gamma[c] * r;
    scale[c] = sc;
    shift[c] = beta[c] - mean * sc;
}

__global__ void bn_apply_relu_kernel(const float4* __restrict__ in,
                                     const float* __restrict__ scale,
                                     const float* __restrict__ shift,
                                     float4* __restrict__ out)
{
    int i = blockIdx.x * 256 + threadIdx.x;
    int c = (i >> 10) & 63;
    float sc = scale[c], sf = shift[c];
    float4 v = in[i];
    v.x = fmaxf(fmaf(v.x, sc, sf), 0.f);
    v.y = fmaxf(fmaf(v.y, sc, sf), 0.f);
    v.z = fmaxf(fmaf(v.z, sc, sf), 0.f);
    v.w = fmaxf(fmaf(v.w, sc, sf), 0.f);
    out[i] = v;
}

__global__ void bn_apply_relu_pack_kernel(const float* __restrict__ in,
                                          const float* __restrict__ scale,
                                          const float* __restrict__ shift,
                                          uint32_t* __restrict__ outp)
{
    int i = blockIdx.x * 256 + threadIdx.x;
    int b  = i >> 17;
    int cp = (i >> 12) & 31;
    int n  = i & 4095;
    size_t base = (((size_t)(b * CC + 2 * cp)) << 12) + n;
    float v0 = fmaxf(fmaf(in[base],        scale[2 * cp],     shift[2 * cp]),     0.f);
    float v1 = fmaxf(fmaf(in[base + 4096], scale[2 * cp + 1], shift[2 * cp + 1]), 0.f);
    __half2 h = __floats2half2_rn(v0, v1);
    outp[i] = *(uint32_t*)&h;
}

// ---------------- flash attention, fp16 MMA, zero-repack layouts --------------
// Qt2: u32 [B,N,32] c-pairs; Kp: u32 [B,32,N] c-pairs; Gp: u32 [B,N/2,64] n-pairs
// -> Y fp32 [B,C,N].  Br=64 (4 warps x 16q), Bc=64.
__global__ void __launch_bounds__(128) flash_f16_kernel(
    const uint32_t* __restrict__ Qt2, const uint32_t* __restrict__ Kp,
    const uint32_t* __restrict__ Gp, float* __restrict__ Y)
{
    __shared__ __align__(16) uint32_t Ks2[32 * 72];   // [c-pair][m]
    __shared__ __align__(16) uint32_t Gs2[32 * 72];   // [m-pair][c]
    __shared__ __align__(16) uint32_t Ps[4 * 16 * 36];

    int b   = blockIdx.y;
    int n0  = blockIdx.x * 64;
    int tid = threadIdx.x;
    int w    = tid >> 5;
    int lane = tid & 31;
    int gid  = lane >> 2;
    int tig  = lane & 3;
    uint32_t* Pw = Ps + w * 576;

    // Q fragments held in regs
    uint32_t aq[4][4];
    {
        const uint32_t* qb2 = Qt2 + ((size_t)(b * NN + n0 + w * 16)) * 32;
#pragma unroll
        for (int kk = 0; kk < 4; kk++) {
            aq[kk][0] = qb2[gid * 32 + 8 * kk + tig];
            aq[kk][1] = qb2[(gid + 8) * 32 + 8 * kk + tig];
            aq[kk][2] = qb2[gid * 32 + 8 * kk + tig + 4];
            aq[kk][3] = qb2[(gid + 8) * 32 + 8 * kk + tig + 4];
        }
    }

    float o[8][4];
#pragma unroll
    for (int nt = 0; nt < 8; nt++)
#pragma unroll
        for (int r = 0; r < 4; r++) o[nt][r] = 0.f;
    float rm0 = -1e30f, rm1 = -1e30f, rl0 = 0.f, rl1 = 0.f;

    for (int j0 = 0; j0 < NN; j0 += 64) {
        __syncthreads();
        for (int i = tid; i < 2048; i += 128) {
            int r = i >> 6, m = i & 63;
            Ks2[r * 72 + m] = Kp[(((size_t)(b * 32 + r)) << 12) + j0 + m];
            Gs2[r * 72 + m] = Gp[((size_t)b * 2048 + (j0 >> 1) + r) * 64 + m];
        }
        __syncthreads();

        // ---- S = Q K : 4 k16 steps x 8 n-tiles ----
        float s[8][4];
#pragma unroll
        for (int nt = 0; nt < 8; nt++)
#pragma unroll
            for (int r = 0; r < 4; r++) s[nt][r] = 0.f;
#pragma unroll
        for (int kk = 0; kk < 4; kk++) {
            const uint32_t* kr0 = Ks2 + (8 * kk + tig) * 72 + gid;
            const uint32_t* kr1 = Ks2 + (8 * kk + tig + 4) * 72 + gid;
#pragma unroll
            for (int nt = 0; nt < 8; nt++)
                mma_f16_k16(s[nt], aq[kk], kr0[8 * nt], kr1[8 * nt]);
        }

        // ---- online softmax ----
        float mx0 = -1e30f, mx1 = -1e30f;
#pragma unroll
        for (int nt = 0; nt < 8; nt++) {
            mx0 = fmaxf(mx0, fmaxf(s[nt][0], s[nt][1]));
            mx1 = fmaxf(mx1, fmaxf(s[nt][2], s[nt][3]));
        }
        mx0 = fmaxf(mx0, __shfl_xor_sync(0xffffffffu, mx0, 1));
        mx0 = fmaxf(mx0, __shfl_xor_sync(0xffffffffu, mx0, 2));
        mx1 = fmaxf(mx1, __shfl_xor_sync(0xffffffffu, mx1, 1));
        mx1 = fmaxf(mx1, __shfl_xor_sync(0xffffffffu, mx1, 2));

        float mn0 = fmaxf(rm0, mx0), mn1 = fmaxf(rm1, mx1);
        float al0 = __expf(rm0 - mn0), al1 = __expf(rm1 - mn1);
        rm0 = mn0; rm1 = mn1;

        float rs0 = 0.f, rs1 = 0.f;
#pragma unroll
        for (int nt = 0; nt < 8; nt++) {
            float p0 = __expf(s[nt][0] - mn0);
            float p1 = __expf(s[nt][1] - mn0);
            float p2 = __expf(s[nt][2] - mn1);
            float p3 = __expf(s[nt][3] - mn1);
            rs0 += p0 + p1; rs1 += p2 + p3;
            __half2 h01 = __floats2half2_rn(p0, p1);
            __half2 h23 = __floats2half2_rn(p2, p3);
            Pw[gid * 36 + 4 * nt + tig] = *(uint32_t*)&h01;
            Pw[(gid + 8) * 36 + 4 * nt + tig] = *(uint32_t*)&h23;
        }
        rs0 += __shfl_xor_sync(0xffffffffu, rs0, 1);
        rs0 += __shfl_xor_sync(0xffffffffu, rs0, 2);
        rs1 += __shfl_xor_sync(0xffffffffu, rs1, 1);
        rs1 += __shfl_xor_sync(0xffffffffu, rs1, 2);
        rl0 = rl0 * al0 + rs0;
        rl1 = rl1 * al1 + rs1;

#pragma unroll
        for (int nt = 0; nt < 8; nt++) {
            o[nt][0] *= al0; o[nt][1] *= al0;
            o[nt][2] *= al1; o[nt][3] *= al1;
        }
        __syncwarp();

        // ---- O += P G : 4 k16 steps ----
#pragma unroll
        for (int kk = 0; kk < 4; kk++) {
            uint32_t pa[4];
            pa[0] = Pw[gid * 36 + 8 * kk + tig];
            pa[1] = Pw[(gid + 8) * 36 + 8 * kk + tig];
            pa[2] = Pw[gid * 36 + 8 * kk + tig + 4];
            pa[3] = Pw[(gid + 8) * 36 + 8 * kk + tig + 4];
            const uint32_t* gr0 = Gs2 + (8 * kk + tig) * 72 + gid;
            const uint32_t* gr1 = Gs2 + (8 * kk + tig + 4) * 72 + gid;
#pragma unroll
            for (int nt = 0; nt < 8; nt++)
                mma_f16_k16(o[nt], pa, gr0[8 * nt], gr1[8 * nt]);
        }
    }

    // ---- epilogue: normalize, stage [q][c] pitch 68, write Y fp32 ----
    __syncthreads();
    float li0 = 1.f / rl0, li1 = 1.f / rl1;
    float* Os = (float*)Ks2;   // 64*68 = 4352 floats (Ks2+Gs2 span 4608 u32)
#pragma unroll
    for (int nt = 0; nt < 8; nt++) {
        float2 v0; v0.x = o[nt][0] * li0; v0.y = o[nt][1] * li0;
        float2 v1; v1.x = o[nt][2] * li1; v1.y = o[nt][3] * li1;
        *(float2*)(Os + (w * 16 + gid) * 68 + 8 * nt + 2 * tig) = v0;
        *(float2*)(Os + (w * 16 + gid + 8) * 68 + 8 * nt + 2 * tig) = v1;
    }
    __syncthreads();
    for (int i = tid; i < 4096; i += 128) {
        int c = i >> 6, q = i & 63;
        Y[(((size_t)(b * CC + c)) << 12) + n0 + q] = Os[q * 68 + c];
    }
}

// ---------------- 1x1 conv + bias + residual -> half2 packed ------------------
__global__ void __launch_bounds__(256) w1x1_res_pack_kernel(
    const float* __restrict__ y, const float* __restrict__ Ww,
    const float* __restrict__ Wb, const float* __restrict__ x,
    uint32_t* __restrict__ zp)
{
    __shared__ float Ws[64 * 65];
    int tid = threadIdx.x;
    for (int i = tid; i < 4096; i += 256) {
        int oc = i >> 6, ic = i & 63;
        Ws[ic * 65 + oc] = Ww[i];
    }
    __syncthreads();

    int og = tid & 3;
    int nl = tid >> 2;
    int gpos = blockIdx.x * 64 + nl;
    int b = gpos >> 12, n = gpos & 4095;
    int oc0 = og * 16;

    float acc[16];
#pragma unroll
    for (int j = 0; j < 16; j++)
        acc[j] = Wb[oc0 + j] + x[(((size_t)(b * CC + oc0 + j)) << 12) + n];

    for (int ic = 0; ic < 64; ic++) {
        float v = y[(((size_t)(b * CC + ic)) << 12) + n];
#pragma unroll
        for (int j = 0; j < 16; j++)
            acc[j] = fmaf(v, Ws[ic * 65 + oc0 + j], acc[j]);
    }
#pragma unroll
    for (int j = 0; j < 16; j += 2) {
        __half2 h = __floats2half2_rn(acc[j], acc[j + 1]);
        zp[(((size_t)(b * 32 + (oc0 >> 1) + (j >> 1))) << 12) + n] = *(uint32_t*)&h;
    }
}

// ---------------- driver -----------------------------------------------------
extern "C" void kernel_launch(void* const* d_in, const int* in_sizes, int n_in,
                              void* d_out, int out_size)
{
    const float* x       = (const float*)d_in[0];
    const float* conv1_w = (const float*)d_in[1];
    const float* bn1_g   = (const float*)d_in[2];
    const float* bn1_b   = (const float*)d_in[3];
    const float* theta_w = (const float*)d_in[4];
    const float* theta_b = (const float*)d_in[5];
    const float* phi_w   = (const float*)d_in[6];
    const float* phi_b   = (const float*)d_in[7];
    const float* g_w     = (const float*)d_in[8];
    const float* g_b     = (const float*)d_in[9];
    const float* W_w     = (const float*)d_in[10];
    const float* W_b     = (const float*)d_in[11];
    const float* conv2_w = (const float*)d_in[12];
    const float* bn2_g   = (const float*)d_in[13];
    const float* bn2_b   = (const float*)d_in[14];
    float* out = (float*)d_out;

    float* buf = nullptr;
    cudaGetSymbolAddress((void**)&buf, g_buf);
    float*    raw   = buf + OFF_RAW;
    float*    ybuf  = buf + OFF_Y;
    uint32_t* th2   = (uint32_t*)(buf + OFF_TH2);
    uint32_t* ph2   = (uint32_t*)(buf + OFF_PH2);
    uint32_t* gp2   = (uint32_t*)(buf + OFF_GP2);
    uint32_t* x1p   = (uint32_t*)(buf + OFF_X1P);
    uint32_t* zp    = (uint32_t*)(buf + OFF_ZP);
    uint32_t* xp    = (uint32_t*)(buf + OFF_XP);
    uint32_t* wpbuf = (uint32_t*)(buf + OFF_WP);
    float*    scale = buf + OFF_SC;
    float*    shift = buf + OFF_SH;
    float*    part  = buf + OFF_PT;

    cudaFuncSetAttribute(conv3x3_f16_kernel,
                         cudaFuncAttributeMaxDynamicSharedMemorySize, CONV_SMEM);

    // weight prep + input pack
    wtrans_f16_kernel<<<400, 256>>>(conv1_w, theta_w, phi_w, g_w, conv2_w, wpbuf);
    pack_x_kernel<<<2048, 256>>>(x, xp);

    // conv1 -> BN -> ReLU (packed output)
    conv3x3_f16_kernel<<<dim3(32, 4, 1), 128, CONV_SMEM>>>(
        xp, wpbuf, nullptr, nullptr, nullptr, raw, raw, raw, 0);
    bn_stats_part_kernel<<<dim3(64, BB), 256>>>(raw, part);
    bn_final_kernel<<<1, 64>>>(part, bn1_g, bn1_b, scale, shift);
    bn_apply_relu_pack_kernel<<<2048, 256>>>(raw, scale, shift, x1p);

    // theta (mode1), phi (mode2), g (mode3) in one launch
    conv3x3_f16_kernel<<<dim3(32, 4, 3), 128, CONV_SMEM>>>(
        x1p, wpbuf + 20480, theta_b, phi_b, g_b,
        th2, ph2, gp2, 1 | (2 << 8) | (3 << 16));

    // attention (fp16 tensor cores, zero-repack)
    flash_f16_kernel<<<dim3(NN / 64, BB), 128>>>(th2, ph2, gp2, ybuf);

    // 1x1 W conv + residual -> packed z
    w1x1_res_pack_kernel<<<256, 256>>>(ybuf, W_w, W_b, x, zp);

    // conv2 -> BN -> ReLU -> out
    conv3x3_f16_kernel<<<dim3(32, 4, 1), 128, CONV_SMEM>>>(
        zp, wpbuf + 4 * 20480, nullptr, nullptr, nullptr, raw, raw, raw, 0);
    bn_stats_part_kernel<<<dim3(64, BB), 256>>>(raw, part);
    bn_final_kernel<<<1, 64>>>(part, bn2_g, bn2_b, scale, shift);
    bn_apply_relu_kernel<<<1024, 256>>>((const float4*)raw, scale, shift, (float4*)out);
}

// round 11
// speedup vs baseline: 1.8761x; 1.1081x over previous
#include <cuda_runtime.h>
#include <cuda_fp16.h>
#include <math.h>
#include <stdint.h>

#define CC 64
#define HH 64
#define WWD 64
#define NN 4096
#define BB 4

// ---------------- scratch (static device memory; no allocs allowed) ----------
__device__ float g_buf[8u * 1024u * 1024u];

static const size_t OFF_RAW = 0;                       // fp32 1M
static const size_t OFF_TH2 = 1u << 20;                // u32 [B,N,32] c-pairs
static const size_t OFF_PH2 = OFF_TH2 + (1u << 19);    // u32 [B,32,N] c-pairs
static const size_t OFF_GP2 = OFF_PH2 + (1u << 19);    // u32 [B,N/2,64] n-pairs
static const size_t OFF_X1P = OFF_GP2 + (1u << 19);    // u32 [B,32,N]
static const size_t OFF_ZP  = OFF_X1P + (1u << 19);
static const size_t OFF_XP  = OFF_ZP + (1u << 19);
static const size_t OFF_WP  = OFF_XP + (1u << 19);     // 5*20480 + 2048 u32
static const size_t OFF_PT  = OFF_WP + 104448;

// ---------------- mma helpers --------------------------------------------------
__device__ __forceinline__ void mma_f16_k16(float c[4], const uint32_t a[4],
                                            uint32_t b0, uint32_t b1) {
    asm volatile(
        "mma.sync.aligned.m16n8k16.row.col.f32.f16.f16.f32 "
        "{%0,%1,%2,%3}, {%4,%5,%6,%7}, {%8,%9}, {%0,%1,%2,%3};"
        : "+f"(c[0]), "+f"(c[1]), "+f"(c[2]), "+f"(c[3])
        : "r"(a[0]), "r"(a[1]), "r"(a[2]), "r"(a[3]), "r"(b0), "r"(b1));
}

__device__ __forceinline__ void mma_f16_k8(float c[4], uint32_t a0, uint32_t a1,
                                           uint32_t b0) {
    asm volatile(
        "mma.sync.aligned.m16n8k8.row.col.f32.f16.f16.f32 "
        "{%0,%1,%2,%3}, {%4,%5}, {%6}, {%0,%1,%2,%3};"
        : "+f"(c[0]), "+f"(c[1]), "+f"(c[2]), "+f"(c[3])
        : "r"(a0), "r"(a1), "r"(b0));
}

// ---------------- weight prep: 5 conv sets + W1x1 --------------------------------
// conv: [s][ch][kp=40][oc=64] half2 (ic-pairs). W1x1: [kp=32][oc=64] half2 (ic-pairs)
__global__ void wtrans_f16_kernel(
    const float* __restrict__ w0, const float* __restrict__ w1,
    const float* __restrict__ w2, const float* __restrict__ w3,
    const float* __restrict__ w4, const float* __restrict__ w1x1,
    uint32_t* __restrict__ wp)
{
    int i = blockIdx.x * 256 + threadIdx.x;
    if (i >= 104448) return;
    if (i >= 102400) {                 // W1x1 pack
        int r = i - 102400;
        int kp = r >> 6, oc = r & 63;
        __half2 h = __floats2half2_rn(w1x1[oc * 64 + 2 * kp],
                                      w1x1[oc * 64 + 2 * kp + 1]);
        wp[i] = *(uint32_t*)&h;
        return;
    }
    int s  = i / 20480;
    int r  = i - s * 20480;
    int ch = r / 2560;
    int r2 = r - ch * 2560;
    int kp = r2 >> 6;
    int oc = r2 & 63;
    uint32_t outv = 0;
    if (kp < 36) {
        const float* w = (s == 0) ? w0 : (s == 1) ? w1 : (s == 2) ? w2 : (s == 3) ? w3 : w4;
        int tap = kp >> 2;
        int icp = kp & 3;
        int ic  = ch * 8 + icp * 2;
        __half2 h = __floats2half2_rn(w[oc * 576 + ic * 9 + tap],
                                      w[oc * 576 + (ic + 1) * 9 + tap]);
        outv = *(uint32_t*)&h;
    }
    wp[i] = outv;
}

// ---------------- pack fp32 [B,C,N] -> half2 [B,C/2,N] -------------------------
__global__ void pack_x_kernel(const float* __restrict__ in, uint32_t* __restrict__ outp)
{
    int i = blockIdx.x * 256 + threadIdx.x;
    int b  = i >> 17;
    int cp = (i >> 12) & 31;
    int n  = i & 4095;
    size_t base = (((size_t)(b * CC + 2 * cp)) << 12) + n;
    __half2 h = __floats2half2_rn(in[base], in[base + 4096]);
    outp[i] = *(uint32_t*)&h;
}

// ---------------- 3x3 conv, fp16 tensor cores (unchanged, proven) --------------
__global__ void __launch_bounds__(128) conv3x3_f16_kernel(
    const uint32_t* __restrict__ inP, const uint32_t* __restrict__ wp,
    const float* __restrict__ bias0, const float* __restrict__ bias1,
    const float* __restrict__ bias2,
    void* __restrict__ out0, void* __restrict__ out1, void* __restrict__ out2,
    int modes)
{
    extern __shared__ __align__(16) uint32_t smc[];
    uint32_t* Aw = smc;            // [40][72]
    uint32_t* Is = smc + 2880;     // [icp=4][r=4][74] icp stride 296

    int s = blockIdx.z;
    const float* bias = (s == 0) ? bias0 : (s == 1) ? bias1 : bias2;
    void* out = (s == 0) ? out0 : (s == 1) ? out1 : out2;
    int mode = (modes >> (8 * s)) & 0xff;
    const uint32_t* wps = wp + (size_t)s * 20480;

    int b   = blockIdx.y;
    int y0  = blockIdx.x * 2;
    int tid = threadIdx.x;
    int w    = tid >> 5;
    int lane = tid & 31;
    int gid  = lane >> 2;
    int tig  = lane & 3;
    int wy = w >> 1;
    int wx = (w & 1) * 32;

    float c[4][4][4];
#pragma unroll
    for (int mt = 0; mt < 4; mt++)
#pragma unroll
        for (int nt = 0; nt < 4; nt++)
#pragma unroll
            for (int r = 0; r < 4; r++) c[mt][nt][r] = 0.f;

    for (int ch = 0; ch < 8; ch++) {
        __syncthreads();
        for (int i = tid; i < 2560; i += 128) {
            int kp = i >> 6, oc = i & 63;
            Aw[kp * 72 + oc] = wps[ch * 2560 + i];
        }
        for (int i = tid; i < 1056; i += 128) {
            int icp = i / 264;
            int rem = i - icp * 264;
            int r   = rem / 66;
            int col = rem - r * 66;
            int gy = y0 + r - 1;
            int gx = col - 1;
            uint32_t v = 0;
            if (gy >= 0 && gy < HH && gx >= 0 && gx < WWD)
                v = inP[(((size_t)(b * 32 + ch * 4 + icp)) << 12) + (gy << 6) + gx];
            Is[icp * 296 + r * 74 + col] = v;
        }
        __syncthreads();

#pragma unroll
        for (int kk = 0; kk < 4; kk++) {
            const int t0 = 2 * kk, t1 = 2 * kk + 1;
            const int ky0 = t0 / 3, kx0 = t0 % 3;
            const int ky1 = t1 / 3, kx1 = t1 % 3;
            uint32_t bf0[4], bf1[4];
#pragma unroll
            for (int nt = 0; nt < 4; nt++) {
                int col = wx + 8 * nt + gid;
                bf0[nt] = Is[tig * 296 + (wy + ky0) * 74 + col + kx0];
                bf1[nt] = Is[tig * 296 + (wy + ky1) * 74 + col + kx1];
            }
#pragma unroll
            for (int mt = 0; mt < 4; mt++) {
                int colA = mt * 16 + gid;
                uint32_t a[4];
                a[0] = Aw[(8 * kk + tig) * 72 + colA];
                a[1] = Aw[(8 * kk + tig) * 72 + colA + 8];
                a[2] = Aw[(8 * kk + tig + 4) * 72 + colA];
                a[3] = Aw[(8 * kk + tig + 4) * 72 + colA + 8];
#pragma unroll
                for (int nt = 0; nt < 4; nt++)
                    mma_f16_k16(c[mt][nt], a, bf0[nt], bf1[nt]);
            }
        }
        {
            uint32_t bf[4];
#pragma unroll
            for (int nt = 0; nt < 4; nt++)
                bf[nt] = Is[tig * 296 + (wy + 2) * 74 + wx + 8 * nt + gid + 2];
#pragma unroll
            for (int mt = 0; mt < 4; mt++) {
                int colA = mt * 16 + gid;
                uint32_t a0 = Aw[(32 + tig) * 72 + colA];
                uint32_t a1 = Aw[(32 + tig) * 72 + colA + 8];
#pragma unroll
                for (int nt = 0; nt < 4; nt++)
                    mma_f16_k8(c[mt][nt], a0, a1, bf[nt]);
            }
        }
    }

    __syncthreads();
    float* Os = (float*)smc;
    float bv0[4], bv1[4];
#pragma unroll
    for (int mt = 0; mt < 4; mt++) {
        bv0[mt] = bias ? bias[mt * 16 + gid] : 0.f;
        bv1[mt] = bias ? bias[mt * 16 + gid + 8] : 0.f;
    }
#pragma unroll
    for (int mt = 0; mt < 4; mt++)
#pragma unroll
        for (int nt = 0; nt < 4; nt++) {
            int n = wx + wy * 64 + nt * 8 + 2 * tig;
            float2 v0, v1;
            v0.x = c[mt][nt][0] + bv0[mt];
            v0.y = c[mt][nt][1] + bv0[mt];
            v1.x = c[mt][nt][2] + bv1[mt];
            v1.y = c[mt][nt][3] + bv1[mt];
            *(float2*)(Os + (mt * 16 + gid) * 130 + n) = v0;
            *(float2*)(Os + (mt * 16 + gid + 8) * 130 + n) = v1;
        }
    __syncthreads();
    int n0 = blockIdx.x * 128;
    if (mode == 0) {
        float* of = (float*)out;
        for (int i = tid; i < 8192; i += 128) {
            int oc = i >> 7, nl = i & 127;
            of[(((size_t)(b * CC + oc)) << 12) + n0 + nl] = Os[oc * 130 + nl];
        }
    } else if (mode == 1) {
        uint32_t* ou = (uint32_t*)out;
        for (int i = tid; i < 4096; i += 128) {
            int nl = i >> 5, ocp = i & 31;
            __half2 h = __floats2half2_rn(Os[2 * ocp * 130 + nl],
                                          Os[(2 * ocp + 1) * 130 + nl]);
            ou[((size_t)(b * NN + n0 + nl)) * 32 + ocp] = *(uint32_t*)&h;
        }
    } else if (mode == 2) {
        uint32_t* ou = (uint32_t*)out;
        for (int i = tid; i < 4096; i += 128) {
            int cp = i >> 7, nl = i & 127;
            __half2 h = __floats2half2_rn(Os[2 * cp * 130 + nl],
                                          Os[(2 * cp + 1) * 130 + nl]);
            ou[(((size_t)(b * 32 + cp)) << 12) + n0 + nl] = *(uint32_t*)&h;
        }
    } else {
        uint32_t* ou = (uint32_t*)out;
        for (int i = tid; i < 4096; i += 128) {
            int np = i >> 6, oc = i & 63;
            __half2 h = __floats2half2_rn(Os[oc * 130 + 2 * np],
                                          Os[oc * 130 + 2 * np + 1]);
            ou[((size_t)b * 2048 + (n0 >> 1) + np) * 64 + oc] = *(uint32_t*)&h;
        }
    }
}
#define CONV_SMEM (33280)

// ---------------- BN stats partials --------------------------------------------
__global__ void bn_stats_part_kernel(const float* __restrict__ in,
                                     float* __restrict__ part)
{
    int c = blockIdx.x, b = blockIdx.y;
    int tid = threadIdx.x;
    const float4* p4 = (const float4*)(in + (((size_t)(b * CC + c)) << 12));
    float s = 0.f, s2 = 0.f;
#pragma unroll
    for (int i = tid; i < 1024; i += 256) {
        float4 v = p4[i];
        s  += v.x + v.y + v.z + v.w;
        s2 += v.x * v.x + v.y * v.y + v.z * v.z + v.w * v.w;
    }
    __shared__ float sh[256], sh2[256];
    sh[tid] = s; sh2[tid] = s2;
    __syncthreads();
    for (int o = 128; o > 0; o >>= 1) {
        if (tid < o) { sh[tid] += sh[tid + o]; sh2[tid] += sh2[tid + o]; }
        __syncthreads();
    }
    if (tid == 0) {
        part[(c * BB + b) * 2]     = sh[0];
        part[(c * BB + b) * 2 + 1] = sh2[0];
    }
}

// helper: per-block recompute of scale/shift from partials (64 channels)
__device__ __forceinline__ void bn_make_scale_shift(
    const float* part, const float* gamma, const float* beta,
    float* sc_s, float* sf_s, int tid)
{
    if (tid < 64) {
        float s = 0.f, s2 = 0.f;
#pragma unroll
        for (int b = 0; b < BB; b++) {
            s  += part[(tid * BB + b) * 2];
            s2 += part[(tid * BB + b) * 2 + 1];
        }
        const float inv = 1.f / (float)(BB * NN);
        float mean = s * inv;
        float var  = s2 * inv - mean * mean;
        float r    = rsqrtf(var + 1e-5f);
        float sc   = gamma[tid] * r;
        sc_s[tid] = sc;
        sf_s[tid] = beta[tid] - mean * sc;
    }
    __syncthreads();
}

__global__ void bn_apply_relu_kernel(const float4* __restrict__ in,
                                     const float* __restrict__ part,
                                     const float* __restrict__ gamma,
                                     const float* __restrict__ beta,
                                     float4* __restrict__ out)
{
    __shared__ float sc_s[64], sf_s[64];
    bn_make_scale_shift(part, gamma, beta, sc_s, sf_s, threadIdx.x);
    int i = blockIdx.x * 256 + threadIdx.x;
    int c = (i >> 10) & 63;
    float sc = sc_s[c], sf = sf_s[c];
    float4 v = in[i];
    v.x = fmaxf(fmaf(v.x, sc, sf), 0.f);
    v.y = fmaxf(fmaf(v.y, sc, sf), 0.f);
    v.z = fmaxf(fmaf(v.z, sc, sf), 0.f);
    v.w = fmaxf(fmaf(v.w, sc, sf), 0.f);
    out[i] = v;
}

__global__ void bn_apply_relu_pack_kernel(const float* __restrict__ in,
                                          const float* __restrict__ part,
                                          const float* __restrict__ gamma,
                                          const float* __restrict__ beta,
                                          uint32_t* __restrict__ outp)
{
    __shared__ float sc_s[64], sf_s[64];
    bn_make_scale_shift(part, gamma, beta, sc_s, sf_s, threadIdx.x);
    int i = blockIdx.x * 256 + threadIdx.x;
    int b  = i >> 17;
    int cp = (i >> 12) & 31;
    int n  = i & 4095;
    size_t base = (((size_t)(b * CC + 2 * cp)) << 12) + n;
    float v0 = fmaxf(fmaf(in[base],        sc_s[2 * cp],     sf_s[2 * cp]),     0.f);
    float v1 = fmaxf(fmaf(in[base + 4096], sc_s[2 * cp + 1], sf_s[2 * cp + 1]), 0.f);
    __half2 h = __floats2half2_rn(v0, v1);
    outp[i] = *(uint32_t*)&h;
}

// ---------------- flash attention Br=128 + fused 1x1 W conv + residual --------
// Qt2 u32 [B,N,32]; Kp u32 [B,32,N]; Gp u32 [B,N/2,64]; W1p u32 [32][64];
// x fp32 [B,C,N] -> zp u32 [B,32,N] (half2 c-pairs), z = W*y + Wb + x
__global__ void __launch_bounds__(256) flash_fused_kernel(
    const uint32_t* __restrict__ Qt2, const uint32_t* __restrict__ Kp,
    const uint32_t* __restrict__ Gp, const uint32_t* __restrict__ W1p,
    const float* __restrict__ W1b, const float* __restrict__ x,
    uint32_t* __restrict__ zp)
{
    __shared__ __align__(16) uint32_t Ks2[32 * 72];   // [c-pair][m]; reused as W
    __shared__ __align__(16) uint32_t Gs2[32 * 72];   // [m-pair][c]
    __shared__ __align__(16) uint32_t Ps[8 * 16 * 36]; // per-warp P; reused as y

    int b   = blockIdx.y;
    int n0  = blockIdx.x * 128;
    int tid = threadIdx.x;
    int w    = tid >> 5;
    int lane = tid & 31;
    int gid  = lane >> 2;
    int tig  = lane & 3;
    uint32_t* Pw = Ps + w * 576;

    uint32_t aq[4][4];
    {
        const uint32_t* qb2 = Qt2 + ((size_t)(b * NN + n0 + w * 16)) * 32;
#pragma unroll
        for (int kk = 0; kk < 4; kk++) {
            aq[kk][0] = qb2[gid * 32 + 8 * kk + tig];
            aq[kk][1] = qb2[(gid + 8) * 32 + 8 * kk + tig];
            aq[kk][2] = qb2[gid * 32 + 8 * kk + tig + 4];
            aq[kk][3] = qb2[(gid + 8) * 32 + 8 * kk + tig + 4];
        }
    }

    float o[8][4];
#pragma unroll
    for (int nt = 0; nt < 8; nt++)
#pragma unroll
        for (int r = 0; r < 4; r++) o[nt][r] = 0.f;
    float rm0 = -1e30f, rm1 = -1e30f, rl0 = 0.f, rl1 = 0.f;

    for (int j0 = 0; j0 < NN; j0 += 64) {
        __syncthreads();
        for (int i = tid; i < 2048; i += 256) {
            int r = i >> 6, m = i & 63;
            Ks2[r * 72 + m] = Kp[(((size_t)(b * 32 + r)) << 12) + j0 + m];
            Gs2[r * 72 + m] = Gp[((size_t)b * 2048 + (j0 >> 1) + r) * 64 + m];
        }
        __syncthreads();

        float s[8][4];
#pragma unroll
        for (int nt = 0; nt < 8; nt++)
#pragma unroll
            for (int r = 0; r < 4; r++) s[nt][r] = 0.f;
#pragma unroll
        for (int kk = 0; kk < 4; kk++) {
            const uint32_t* kr0 = Ks2 + (8 * kk + tig) * 72 + gid;
            const uint32_t* kr1 = Ks2 + (8 * kk + tig + 4) * 72 + gid;
#pragma unroll
            for (int nt = 0; nt < 8; nt++)
                mma_f16_k16(s[nt], aq[kk], kr0[8 * nt], kr1[8 * nt]);
        }

        float mx0 = -1e30f, mx1 = -1e30f;
#pragma unroll
        for (int nt = 0; nt < 8; nt++) {
            mx0 = fmaxf(mx0, fmaxf(s[nt][0], s[nt][1]));
            mx1 = fmaxf(mx1, fmaxf(s[nt][2], s[nt][3]));
        }
        mx0 = fmaxf(mx0, __shfl_xor_sync(0xffffffffu, mx0, 1));
        mx0 = fmaxf(mx0, __shfl_xor_sync(0xffffffffu, mx0, 2));
        mx1 = fmaxf(mx1, __shfl_xor_sync(0xffffffffu, mx1, 1));
        mx1 = fmaxf(mx1, __shfl_xor_sync(0xffffffffu, mx1, 2));

        float mn0 = fmaxf(rm0, mx0), mn1 = fmaxf(rm1, mx1);
        float al0 = __expf(rm0 - mn0), al1 = __expf(rm1 - mn1);
        rm0 = mn0; rm1 = mn1;

        float rs0 = 0.f, rs1 = 0.f;
#pragma unroll
        for (int nt = 0; nt < 8; nt++) {
            float p0 = __expf(s[nt][0] - mn0);
            float p1 = __expf(s[nt][1] - mn0);
            float p2 = __expf(s[nt][2] - mn1);
            float p3 = __expf(s[nt][3] - mn1);
            rs0 += p0 + p1; rs1 += p2 + p3;
            __half2 h01 = __floats2half2_rn(p0, p1);
            __half2 h23 = __floats2half2_rn(p2, p3);
            Pw[gid * 36 + 4 * nt + tig] = *(uint32_t*)&h01;
            Pw[(gid + 8) * 36 + 4 * nt + tig] = *(uint32_t*)&h23;
        }
        rs0 += __shfl_xor_sync(0xffffffffu, rs0, 1);
        rs0 += __shfl_xor_sync(0xffffffffu, rs0, 2);
        rs1 += __shfl_xor_sync(0xffffffffu, rs1, 1);
        rs1 += __shfl_xor_sync(0xffffffffu, rs1, 2);
        rl0 = rl0 * al0 + rs0;
        rl1 = rl1 * al1 + rs1;

#pragma unroll
        for (int nt = 0; nt < 8; nt++) {
            o[nt][0] *= al0; o[nt][1] *= al0;
            o[nt][2] *= al1; o[nt][3] *= al1;
        }
        __syncwarp();

#pragma unroll
        for (int kk = 0; kk < 4; kk++) {
            uint32_t pa[4];
            pa[0] = Pw[gid * 36 + 8 * kk + tig];
            pa[1] = Pw[(gid + 8) * 36 + 8 * kk + tig];
            pa[2] = Pw[gid * 36 + 8 * kk + tig + 4];
            pa[3] = Pw[(gid + 8) * 36 + 8 * kk + tig + 4];
            const uint32_t* gr0 = Gs2 + (8 * kk + tig) * 72 + gid;
            const uint32_t* gr1 = Gs2 + (8 * kk + tig + 4) * 72 + gid;
#pragma unroll
            for (int nt = 0; nt < 8; nt++)
                mma_f16_k16(o[nt], pa, gr0[8 * nt], gr1[8 * nt]);
        }
    }

    // ---- fused epilogue: y staged as half2 c-pairs; z = W*y + Wb + x ----
    __syncthreads();                       // all warps done reading Ks2/Gs2/Ps
    float li0 = 1.f / rl0, li1 = 1.f / rl1;
    uint32_t* Ys = Ps;                     // [128 q][36] c-pairs (own-warp region)
#pragma unroll
    for (int nt = 0; nt < 8; nt++) {
        __half2 h01 = __floats2half2_rn(o[nt][0] * li0, o[nt][1] * li0);
        __half2 h23 = __floats2half2_rn(o[nt][2] * li1, o[nt][3] * li1);
        Ys[(w * 16 + gid) * 36 + 4 * nt + tig] = *(uint32_t*)&h01;
        Ys[(w * 16 + gid + 8) * 36 + 4 * nt + tig] = *(uint32_t*)&h23;
    }
    // load W into Ks2 region: [kp=32][oc=64] pitch 72
    for (int i = tid; i < 2048; i += 256) {
        int kp = i >> 6, oc = i & 63;
        Ks2[kp * 72 + oc] = W1p[i];
    }
    __syncthreads();

    float d[8][4];
#pragma unroll
    for (int nt = 0; nt < 8; nt++)
#pragma unroll
        for (int r = 0; r < 4; r++) d[nt][r] = 0.f;
#pragma unroll
    for (int kk = 0; kk < 4; kk++) {
        uint32_t pa[4];
        pa[0] = Ys[(w * 16 + gid) * 36 + 8 * kk + tig];
        pa[1] = Ys[(w * 16 + gid + 8) * 36 + 8 * kk + tig];
        pa[2] = Ys[(w * 16 + gid) * 36 + 8 * kk + tig + 4];
        pa[3] = Ys[(w * 16 + gid + 8) * 36 + 8 * kk + tig + 4];
        const uint32_t* wr0 = Ks2 + (8 * kk + tig) * 72 + gid;
        const uint32_t* wr1 = Ks2 + (8 * kk + tig + 4) * 72 + gid;
#pragma unroll
        for (int nt = 0; nt < 8; nt++)
            mma_f16_k16(d[nt], pa, wr0[8 * nt], wr1[8 * nt]);
    }

    // bias + residual (fp32) + pack to zp [B,32,N]
#pragma unroll
    for (int nt = 0; nt < 8; nt++) {
        int oc0 = 8 * nt + 2 * tig;
        float b0 = W1b[oc0], b1 = W1b[oc0 + 1];
        int n  = n0 + w * 16 + gid;
        size_t x0 = (((size_t)(b * CC + oc0)) << 12);
        float z0 = d[nt][0] + b0 + x[x0 + n];
        float z1 = d[nt][1] + b1 + x[x0 + 4096 + n];
        float z2 = d[nt][2] + b0 + x[x0 + n + 8];
        float z3 = d[nt][3] + b1 + x[x0 + 4096 + n + 8];
        __half2 h01 = __floats2half2_rn(z0, z1);
        __half2 h23 = __floats2half2_rn(z2, z3);
        size_t zbase = (((size_t)(b * 32 + 4 * nt + tig)) << 12);
        zp[zbase + n]     = *(uint32_t*)&h01;
        zp[zbase + n + 8] = *(uint32_t*)&h23;
    }
}

// ---------------- driver -----------------------------------------------------
extern "C" void kernel_launch(void* const* d_in, const int* in_sizes, int n_in,
                              void* d_out, int out_size)
{
    const float* x       = (const float*)d_in[0];
    const float* conv1_w = (const float*)d_in[1];
    const float* bn1_g   = (const float*)d_in[2];
    const float* bn1_b   = (const float*)d_in[3];
    const float* theta_w = (const float*)d_in[4];
    const float* theta_b = (const float*)d_in[5];
    const float* phi_w   = (const float*)d_in[6];
    const float* phi_b   = (const float*)d_in[7];
    const float* g_w     = (const float*)d_in[8];
    const float* g_b     = (const float*)d_in[9];
    const float* W_w     = (const float*)d_in[10];
    const float* W_b     = (const float*)d_in[11];
    const float* conv2_w = (const float*)d_in[12];
    const float* bn2_g   = (const float*)d_in[13];
    const float* bn2_b   = (const float*)d_in[14];
    float* out = (float*)d_out;

    float* buf = nullptr;
    cudaGetSymbolAddress((void**)&buf, g_buf);
    float*    raw   = buf + OFF_RAW;
    uint32_t* th2   = (uint32_t*)(buf + OFF_TH2);
    uint32_t* ph2   = (uint32_t*)(buf + OFF_PH2);
    uint32_t* gp2   = (uint32_t*)(buf + OFF_GP2);
    uint32_t* x1p   = (uint32_t*)(buf + OFF_X1P);
    uint32_t* zp    = (uint32_t*)(buf + OFF_ZP);
    uint32_t* xp    = (uint32_t*)(buf + OFF_XP);
    uint32_t* wpbuf = (uint32_t*)(buf + OFF_WP);
    float*    part  = buf + OFF_PT;

    cudaFuncSetAttribute(conv3x3_f16_kernel,
                         cudaFuncAttributeMaxDynamicSharedMemorySize, CONV_SMEM);

    // weight prep (5 conv sets + W1x1) + input pack
    wtrans_f16_kernel<<<408, 256>>>(conv1_w, theta_w, phi_w, g_w, conv2_w, W_w, wpbuf);
    pack_x_kernel<<<2048, 256>>>(x, xp);

    // conv1 -> BN -> ReLU (packed output)
    conv3x3_f16_kernel<<<dim3(32, 4, 1), 128, CONV_SMEM>>>(
        xp, wpbuf, nullptr, nullptr, nullptr, raw, raw, raw, 0);
    bn_stats_part_kernel<<<dim3(64, BB), 256>>>(raw, part);
    bn_apply_relu_pack_kernel<<<2048, 256>>>(raw, part, bn1_g, bn1_b, x1p);

    // theta (mode1), phi (mode2), g (mode3) in one launch
    conv3x3_f16_kernel<<<dim3(32, 4, 3), 128, CONV_SMEM>>>(
        x1p, wpbuf + 20480, theta_b, phi_b, g_b,
        th2, ph2, gp2, 1 | (2 << 8) | (3 << 16));

    // attention + fused 1x1 W conv + residual -> zp
    flash_fused_kernel<<<dim3(NN / 128, BB), 256>>>(
        th2, ph2, gp2, wpbuf + 102400, W_b, x, zp);

    // conv2 -> BN -> ReLU -> out
    conv3x3_f16_kernel<<<dim3(32, 4, 1), 128, CONV_SMEM>>>(
        zp, wpbuf + 4 * 20480, nullptr, nullptr, nullptr, raw, raw, raw, 0);
    bn_stats_part_kernel<<<dim3(64, BB), 256>>>(raw, part);
    bn_apply_relu_kernel<<<1024, 256>>>((const float4*)raw, part, bn2_g, bn2_b,
                                        (float4*)out);
}

// round 12
// speedup vs baseline: 1.9094x; 1.0177x over previous
#include <cuda_runtime.h>
#include <cuda_fp16.h>
#include <math.h>
#include <stdint.h>

#define CC 64
#define HH 64
#define WWD 64
#define NN 4096
#define BB 4

// ---------------- scratch (static device memory; no allocs allowed) ----------
__device__ float g_buf[8u * 1024u * 1024u];

static const size_t OFF_RAW = 0;                       // fp32 1M
static const size_t OFF_TH2 = 1u << 20;                // u32 [B,N,32] c-pairs
static const size_t OFF_PH2 = OFF_TH2 + (1u << 19);    // u32 [B,32,N] c-pairs
static const size_t OFF_GP2 = OFF_PH2 + (1u << 19);    // u32 [B,N/2,64] n-pairs
static const size_t OFF_X1P = OFF_GP2 + (1u << 19);    // u32 [B,32,N]
static const size_t OFF_ZP  = OFF_X1P + (1u << 19);
static const size_t OFF_WP  = OFF_ZP + (1u << 19);     // 5*20480 + 2048 u32
static const size_t OFF_PT1 = OFF_WP + 104448;         // 128 floats (sum,sumsq)*64
static const size_t OFF_PT2 = OFF_PT1 + 128;

// ---------------- mma helpers --------------------------------------------------
__device__ __forceinline__ void mma_f16_k16(float c[4], const uint32_t a[4],
                                            uint32_t b0, uint32_t b1) {
    asm volatile(
        "mma.sync.aligned.m16n8k16.row.col.f32.f16.f16.f32 "
        "{%0,%1,%2,%3}, {%4,%5,%6,%7}, {%8,%9}, {%0,%1,%2,%3};"
        : "+f"(c[0]), "+f"(c[1]), "+f"(c[2]), "+f"(c[3])
        : "r"(a[0]), "r"(a[1]), "r"(a[2]), "r"(a[3]), "r"(b0), "r"(b1));
}

__device__ __forceinline__ void mma_f16_k8(float c[4], uint32_t a0, uint32_t a1,
                                           uint32_t b0) {
    asm volatile(
        "mma.sync.aligned.m16n8k8.row.col.f32.f16.f16.f32 "
        "{%0,%1,%2,%3}, {%4,%5}, {%6}, {%0,%1,%2,%3};"
        : "+f"(c[0]), "+f"(c[1]), "+f"(c[2]), "+f"(c[3])
        : "r"(a0), "r"(a1), "r"(b0));
}

// ---------------- weight prep: 5 conv sets + W1x1 + zero partials --------------
__global__ void wtrans_f16_kernel(
    const float* __restrict__ w0, const float* __restrict__ w1,
    const float* __restrict__ w2, const float* __restrict__ w3,
    const float* __restrict__ w4, const float* __restrict__ w1x1,
    uint32_t* __restrict__ wp, float* __restrict__ partz)
{
    if (blockIdx.x == 0 && threadIdx.x < 256) partz[threadIdx.x] = 0.f;
    int i = blockIdx.x * 256 + threadIdx.x;
    if (i >= 104448) return;
    if (i >= 102400) {                 // W1x1 pack
        int r = i - 102400;
        int kp = r >> 6, oc = r & 63;
        __half2 h = __floats2half2_rn(w1x1[oc * 64 + 2 * kp],
                                      w1x1[oc * 64 + 2 * kp + 1]);
        wp[i] = *(uint32_t*)&h;
        return;
    }
    int s  = i / 20480;
    int r  = i - s * 20480;
    int ch = r / 2560;
    int r2 = r - ch * 2560;
    int kp = r2 >> 6;
    int oc = r2 & 63;
    uint32_t outv = 0;
    if (kp < 36) {
        const float* w = (s == 0) ? w0 : (s == 1) ? w1 : (s == 2) ? w2 : (s == 3) ? w3 : w4;
        int tap = kp >> 2;
        int icp = kp & 3;
        int ic  = ch * 8 + icp * 2;
        __half2 h = __floats2half2_rn(w[oc * 576 + ic * 9 + tap],
                                      w[oc * 576 + (ic + 1) * 9 + tap]);
        outv = *(uint32_t*)&h;
    }
    wp[i] = outv;
}

// ---------------- 3x3 conv, fp16 tensor cores ---------------------------------
// in_fp32: input is fp32 [B,C,N] (converted at staging); else half2 [B,32,N].
// statsPart != null && mode==0: epilogue atomically accumulates per-channel
// sum/sumsq into statsPart[2c],[2c+1].
__global__ void __launch_bounds__(128) conv3x3_f16_kernel(
    const void* __restrict__ inRaw, const uint32_t* __restrict__ wp,
    const float* __restrict__ bias0, const float* __restrict__ bias1,
    const float* __restrict__ bias2,
    void* __restrict__ out0, void* __restrict__ out1, void* __restrict__ out2,
    int modes, int in_fp32, float* __restrict__ statsPart)
{
    extern __shared__ __align__(16) uint32_t smc[];
    uint32_t* Aw = smc;            // [40][72]
    uint32_t* Is = smc + 2880;     // [icp=4][r=4][74] icp stride 296

    int s = blockIdx.z;
    const float* bias = (s == 0) ? bias0 : (s == 1) ? bias1 : bias2;
    void* out = (s == 0) ? out0 : (s == 1) ? out1 : out2;
    int mode = (modes >> (8 * s)) & 0xff;
    const uint32_t* wps = wp + (size_t)s * 20480;
    const uint32_t* inP = (const uint32_t*)inRaw;
    const float* inF = (const float*)inRaw;

    int b   = blockIdx.y;
    int y0  = blockIdx.x * 2;
    int tid = threadIdx.x;
    int w    = tid >> 5;
    int lane = tid & 31;
    int gid  = lane >> 2;
    int tig  = lane & 3;
    int wy = w >> 1;
    int wx = (w & 1) * 32;

    float c[4][4][4];
#pragma unroll
    for (int mt = 0; mt < 4; mt++)
#pragma unroll
        for (int nt = 0; nt < 4; nt++)
#pragma unroll
            for (int r = 0; r < 4; r++) c[mt][nt][r] = 0.f;

    for (int ch = 0; ch < 8; ch++) {
        __syncthreads();
        for (int i = tid; i < 2560; i += 128) {
            int kp = i >> 6, oc = i & 63;
            Aw[kp * 72 + oc] = wps[ch * 2560 + i];
        }
        for (int i = tid; i < 1056; i += 128) {
            int icp = i / 264;
            int rem = i - icp * 264;
            int r   = rem / 66;
            int col = rem - r * 66;
            int gy = y0 + r - 1;
            int gx = col - 1;
            uint32_t v = 0;
            if (gy >= 0 && gy < HH && gx >= 0 && gx < WWD) {
                if (!in_fp32) {
                    v = inP[(((size_t)(b * 32 + ch * 4 + icp)) << 12) + (gy << 6) + gx];
                } else {
                    size_t fb = (((size_t)(b * CC + ch * 8 + 2 * icp)) << 12) + (gy << 6) + gx;
                    __half2 h = __floats2half2_rn(inF[fb], inF[fb + 4096]);
                    v = *(uint32_t*)&h;
                }
            }
            Is[icp * 296 + r * 74 + col] = v;
        }
        __syncthreads();

#pragma unroll
        for (int kk = 0; kk < 4; kk++) {
            const int t0 = 2 * kk, t1 = 2 * kk + 1;
            const int ky0 = t0 / 3, kx0 = t0 % 3;
            const int ky1 = t1 / 3, kx1 = t1 % 3;
            uint32_t bf0[4], bf1[4];
#pragma unroll
            for (int nt = 0; nt < 4; nt++) {
                int col = wx + 8 * nt + gid;
                bf0[nt] = Is[tig * 296 + (wy + ky0) * 74 + col + kx0];
                bf1[nt] = Is[tig * 296 + (wy + ky1) * 74 + col + kx1];
            }
#pragma unroll
            for (int mt = 0; mt < 4; mt++) {
                int colA = mt * 16 + gid;
                uint32_t a[4];
                a[0] = Aw[(8 * kk + tig) * 72 + colA];
                a[1] = Aw[(8 * kk + tig) * 72 + colA + 8];
                a[2] = Aw[(8 * kk + tig + 4) * 72 + colA];
                a[3] = Aw[(8 * kk + tig + 4) * 72 + colA + 8];
#pragma unroll
                for (int nt = 0; nt < 4; nt++)
                    mma_f16_k16(c[mt][nt], a, bf0[nt], bf1[nt]);
            }
        }
        {
            uint32_t bf[4];
#pragma unroll
            for (int nt = 0; nt < 4; nt++)
                bf[nt] = Is[tig * 296 + (wy + 2) * 74 + wx + 8 * nt + gid + 2];
#pragma unroll
            for (int mt = 0; mt < 4; mt++) {
                int colA = mt * 16 + gid;
                uint32_t a0 = Aw[(32 + tig) * 72 + colA];
                uint32_t a1 = Aw[(32 + tig) * 72 + colA + 8];
#pragma unroll
                for (int nt = 0; nt < 4; nt++)
                    mma_f16_k8(c[mt][nt], a0, a1, bf[nt]);
            }
        }
    }

    __syncthreads();
    float* Os = (float*)smc;
    float bv0[4], bv1[4];
#pragma unroll
    for (int mt = 0; mt < 4; mt++) {
        bv0[mt] = bias ? bias[mt * 16 + gid] : 0.f;
        bv1[mt] = bias ? bias[mt * 16 + gid + 8] : 0.f;
    }
#pragma unroll
    for (int mt = 0; mt < 4; mt++)
#pragma unroll
        for (int nt = 0; nt < 4; nt++) {
            int n = wx + wy * 64 + nt * 8 + 2 * tig;
            float2 v0, v1;
            v0.x = c[mt][nt][0] + bv0[mt];
            v0.y = c[mt][nt][1] + bv0[mt];
            v1.x = c[mt][nt][2] + bv1[mt];
            v1.y = c[mt][nt][3] + bv1[mt];
            *(float2*)(Os + (mt * 16 + gid) * 130 + n) = v0;
            *(float2*)(Os + (mt * 16 + gid + 8) * 130 + n) = v1;
        }
    __syncthreads();
    int n0 = blockIdx.x * 128;
    if (mode == 0) {
        float* of = (float*)out;
        for (int i = tid; i < 8192; i += 128) {
            int oc = i >> 7, nl = i & 127;
            of[(((size_t)(b * CC + oc)) << 12) + n0 + nl] = Os[oc * 130 + nl];
        }
        if (statsPart) {
            // per-channel partial sums over this 128-px tile
            int oc = tid >> 1, half = tid & 1;
            const float* row = Os + oc * 130 + half * 64;
            float s1 = 0.f, s2 = 0.f;
#pragma unroll
            for (int j = 0; j < 64; j++) {
                float v = row[j];
                s1 += v; s2 += v * v;
            }
            s1 += __shfl_xor_sync(0xffffffffu, s1, 1);
            s2 += __shfl_xor_sync(0xffffffffu, s2, 1);
            if (half == 0) {
                atomicAdd(statsPart + 2 * oc, s1);
                atomicAdd(statsPart + 2 * oc + 1, s2);
            }
        }
    } else if (mode == 1) {
        uint32_t* ou = (uint32_t*)out;
        for (int i = tid; i < 4096; i += 128) {
            int nl = i >> 5, ocp = i & 31;
            __half2 h = __floats2half2_rn(Os[2 * ocp * 130 + nl],
                                          Os[(2 * ocp + 1) * 130 + nl]);
            ou[((size_t)(b * NN + n0 + nl)) * 32 + ocp] = *(uint32_t*)&h;
        }
    } else if (mode == 2) {
        uint32_t* ou = (uint32_t*)out;
        for (int i = tid; i < 4096; i += 128) {
            int cp = i >> 7, nl = i & 127;
            __half2 h = __floats2half2_rn(Os[2 * cp * 130 + nl],
                                          Os[(2 * cp + 1) * 130 + nl]);
            ou[(((size_t)(b * 32 + cp)) << 12) + n0 + nl] = *(uint32_t*)&h;
        }
    } else {
        uint32_t* ou = (uint32_t*)out;
        for (int i = tid; i < 4096; i += 128) {
            int np = i >> 6, oc = i & 63;
            __half2 h = __floats2half2_rn(Os[oc * 130 + 2 * np],
                                          Os[oc * 130 + 2 * np + 1]);
            ou[((size_t)b * 2048 + (n0 >> 1) + np) * 64 + oc] = *(uint32_t*)&h;
        }
    }
}
#define CONV_SMEM (33280)

// helper: per-block recompute of scale/shift from fused partials
__device__ __forceinline__ void bn_make_scale_shift(
    const float* part, const float* gamma, const float* beta,
    float* sc_s, float* sf_s, int tid)
{
    if (tid < 64) {
        float s  = part[2 * tid];
        float s2 = part[2 * tid + 1];
        const float inv = 1.f / (float)(BB * NN);
        float mean = s * inv;
        float var  = s2 * inv - mean * mean;
        float r    = rsqrtf(var + 1e-5f);
        float sc   = gamma[tid] * r;
        sc_s[tid] = sc;
        sf_s[tid] = beta[tid] - mean * sc;
    }
    __syncthreads();
}

__global__ void bn_apply_relu_kernel(const float4* __restrict__ in,
                                     const float* __restrict__ part,
                                     const float* __restrict__ gamma,
                                     const float* __restrict__ beta,
                                     float4* __restrict__ out)
{
    __shared__ float sc_s[64], sf_s[64];
    bn_make_scale_shift(part, gamma, beta, sc_s, sf_s, threadIdx.x);
    int i = blockIdx.x * 256 + threadIdx.x;
    int c = (i >> 10) & 63;
    float sc = sc_s[c], sf = sf_s[c];
    float4 v = in[i];
    v.x = fmaxf(fmaf(v.x, sc, sf), 0.f);
    v.y = fmaxf(fmaf(v.y, sc, sf), 0.f);
    v.z = fmaxf(fmaf(v.z, sc, sf), 0.f);
    v.w = fmaxf(fmaf(v.w, sc, sf), 0.f);
    out[i] = v;
}

__global__ void bn_apply_relu_pack_kernel(const float* __restrict__ in,
                                          const float* __restrict__ part,
                                          const float* __restrict__ gamma,
                                          const float* __restrict__ beta,
                                          uint32_t* __restrict__ outp)
{
    __shared__ float sc_s[64], sf_s[64];
    bn_make_scale_shift(part, gamma, beta, sc_s, sf_s, threadIdx.x);
    int i = blockIdx.x * 256 + threadIdx.x;
    int b  = i >> 17;
    int cp = (i >> 12) & 31;
    int n  = i & 4095;
    size_t base = (((size_t)(b * CC + 2 * cp)) << 12) + n;
    float v0 = fmaxf(fmaf(in[base],        sc_s[2 * cp],     sf_s[2 * cp]),     0.f);
    float v1 = fmaxf(fmaf(in[base + 4096], sc_s[2 * cp + 1], sf_s[2 * cp + 1]), 0.f);
    __half2 h = __floats2half2_rn(v0, v1);
    outp[i] = *(uint32_t*)&h;
}

// ---------------- flash attention Br=128 + fused 1x1 W conv + residual --------
__global__ void __launch_bounds__(256) flash_fused_kernel(
    const uint32_t* __restrict__ Qt2, const uint32_t* __restrict__ Kp,
    const uint32_t* __restrict__ Gp, const uint32_t* __restrict__ W1p,
    const float* __restrict__ W1b, const float* __restrict__ x,
    uint32_t* __restrict__ zp)
{
    __shared__ __align__(16) uint32_t Ks2[32 * 72];   // [c-pair][m]; reused as W
    __shared__ __align__(16) uint32_t Gs2[32 * 72];   // [m-pair][c]
    __shared__ __align__(16) uint32_t Ps[8 * 16 * 36]; // per-warp P; reused as y

    int b   = blockIdx.y;
    int n0  = blockIdx.x * 128;
    int tid = threadIdx.x;
    int w    = tid >> 5;
    int lane = tid & 31;
    int gid  = lane >> 2;
    int tig  = lane & 3;
    uint32_t* Pw = Ps + w * 576;

    uint32_t aq[4][4];
    {
        const uint32_t* qb2 = Qt2 + ((size_t)(b * NN + n0 + w * 16)) * 32;
#pragma unroll
        for (int kk = 0; kk < 4; kk++) {
            aq[kk][0] = qb2[gid * 32 + 8 * kk + tig];
            aq[kk][1] = qb2[(gid + 8) * 32 + 8 * kk + tig];
            aq[kk][2] = qb2[gid * 32 + 8 * kk + tig + 4];
            aq[kk][3] = qb2[(gid + 8) * 32 + 8 * kk + tig + 4];
        }
    }

    float o[8][4];
#pragma unroll
    for (int nt = 0; nt < 8; nt++)
#pragma unroll
        for (int r = 0; r < 4; r++) o[nt][r] = 0.f;
    float rm0 = -1e30f, rm1 = -1e30f, rl0 = 0.f, rl1 = 0.f;

    for (int j0 = 0; j0 < NN; j0 += 64) {
        __syncthreads();
        for (int i = tid; i < 2048; i += 256) {
            int r = i >> 6, m = i & 63;
            Ks2[r * 72 + m] = Kp[(((size_t)(b * 32 + r)) << 12) + j0 + m];
            Gs2[r * 72 + m] = Gp[((size_t)b * 2048 + (j0 >> 1) + r) * 64 + m];
        }
        __syncthreads();

        float s[8][4];
#pragma unroll
        for (int nt = 0; nt < 8; nt++)
#pragma unroll
            for (int r = 0; r < 4; r++) s[nt][r] = 0.f;
#pragma unroll
        for (int kk = 0; kk < 4; kk++) {
            const uint32_t* kr0 = Ks2 + (8 * kk + tig) * 72 + gid;
            const uint32_t* kr1 = Ks2 + (8 * kk + tig + 4) * 72 + gid;
#pragma unroll
            for (int nt = 0; nt < 8; nt++)
                mma_f16_k16(s[nt], aq[kk], kr0[8 * nt], kr1[8 * nt]);
        }

        float mx0 = -1e30f, mx1 = -1e30f;
#pragma unroll
        for (int nt = 0; nt < 8; nt++) {
            mx0 = fmaxf(mx0, fmaxf(s[nt][0], s[nt][1]));
            mx1 = fmaxf(mx1, fmaxf(s[nt][2], s[nt][3]));
        }
        mx0 = fmaxf(mx0, __shfl_xor_sync(0xffffffffu, mx0, 1));
        mx0 = fmaxf(mx0, __shfl_xor_sync(0xffffffffu, mx0, 2));
        mx1 = fmaxf(mx1, __shfl_xor_sync(0xffffffffu, mx1, 1));
        mx1 = fmaxf(mx1, __shfl_xor_sync(0xffffffffu, mx1, 2));

        float mn0 = fmaxf(rm0, mx0), mn1 = fmaxf(rm1, mx1);
        float al0 = __expf(rm0 - mn0), al1 = __expf(rm1 - mn1);
        rm0 = mn0; rm1 = mn1;

        float rs0 = 0.f, rs1 = 0.f;
#pragma unroll
        for (int nt = 0; nt < 8; nt++) {
            float p0 = __expf(s[nt][0] - mn0);
            float p1 = __expf(s[nt][1] - mn0);
            float p2 = __expf(s[nt][2] - mn1);
            float p3 = __expf(s[nt][3] - mn1);
            rs0 += p0 + p1; rs1 += p2 + p3;
            __half2 h01 = __floats2half2_rn(p0, p1);
            __half2 h23 = __floats2half2_rn(p2, p3);
            Pw[gid * 36 + 4 * nt + tig] = *(uint32_t*)&h01;
            Pw[(gid + 8) * 36 + 4 * nt + tig] = *(uint32_t*)&h23;
        }
        rs0 += __shfl_xor_sync(0xffffffffu, rs0, 1);
        rs0 += __shfl_xor_sync(0xffffffffu, rs0, 2);
        rs1 += __shfl_xor_sync(0xffffffffu, rs1, 1);
        rs1 += __shfl_xor_sync(0xffffffffu, rs1, 2);
        rl0 = rl0 * al0 + rs0;
        rl1 = rl1 * al1 + rs1;

#pragma unroll
        for (int nt = 0; nt < 8; nt++) {
            o[nt][0] *= al0; o[nt][1] *= al0;
            o[nt][2] *= al1; o[nt][3] *= al1;
        }
        __syncwarp();

#pragma unroll
        for (int kk = 0; kk < 4; kk++) {
            uint32_t pa[4];
            pa[0] = Pw[gid * 36 + 8 * kk + tig];
            pa[1] = Pw[(gid + 8) * 36 + 8 * kk + tig];
            pa[2] = Pw[gid * 36 + 8 * kk + tig + 4];
            pa[3] = Pw[(gid + 8) * 36 + 8 * kk + tig + 4];
            const uint32_t* gr0 = Gs2 + (8 * kk + tig) * 72 + gid;
            const uint32_t* gr1 = Gs2 + (8 * kk + tig + 4) * 72 + gid;
#pragma unroll
            for (int nt = 0; nt < 8; nt++)
                mma_f16_k16(o[nt], pa, gr0[8 * nt], gr1[8 * nt]);
        }
    }

    // ---- fused epilogue: y staged as half2 c-pairs; z = W*y + Wb + x ----
    __syncthreads();
    float li0 = 1.f / rl0, li1 = 1.f / rl1;
    uint32_t* Ys = Ps;
#pragma unroll
    for (int nt = 0; nt < 8; nt++) {
        __half2 h01 = __floats2half2_rn(o[nt][0] * li0, o[nt][1] * li0);
        __half2 h23 = __floats2half2_rn(o[nt][2] * li1, o[nt][3] * li1);
        Ys[(w * 16 + gid) * 36 + 4 * nt + tig] = *(uint32_t*)&h01;
        Ys[(w * 16 + gid + 8) * 36 + 4 * nt + tig] = *(uint32_t*)&h23;
    }
    for (int i = tid; i < 2048; i += 256) {
        int kp = i >> 6, oc = i & 63;
        Ks2[kp * 72 + oc] = W1p[i];
    }
    __syncthreads();

    float d[8][4];
#pragma unroll
    for (int nt = 0; nt < 8; nt++)
#pragma unroll
        for (int r = 0; r < 4; r++) d[nt][r] = 0.f;
#pragma unroll
    for (int kk = 0; kk < 4; kk++) {
        uint32_t pa[4];
        pa[0] = Ys[(w * 16 + gid) * 36 + 8 * kk + tig];
        pa[1] = Ys[(w * 16 + gid + 8) * 36 + 8 * kk + tig];
        pa[2] = Ys[(w * 16 + gid) * 36 + 8 * kk + tig + 4];
        pa[3] = Ys[(w * 16 + gid + 8) * 36 + 8 * kk + tig + 4];
        const uint32_t* wr0 = Ks2 + (8 * kk + tig) * 72 + gid;
        const uint32_t* wr1 = Ks2 + (8 * kk + tig + 4) * 72 + gid;
#pragma unroll
        for (int nt = 0; nt < 8; nt++)
            mma_f16_k16(d[nt], pa, wr0[8 * nt], wr1[8 * nt]);
    }

#pragma unroll
    for (int nt = 0; nt < 8; nt++) {
        int oc0 = 8 * nt + 2 * tig;
        float b0 = W1b[oc0], b1 = W1b[oc0 + 1];
        int n  = n0 + w * 16 + gid;
        size_t x0 = (((size_t)(b * CC + oc0)) << 12);
        float z0 = d[nt][0] + b0 + x[x0 + n];
        float z1 = d[nt][1] + b1 + x[x0 + 4096 + n];
        float z2 = d[nt][2] + b0 + x[x0 + n + 8];
        float z3 = d[nt][3] + b1 + x[x0 + 4096 + n + 8];
        __half2 h01 = __floats2half2_rn(z0, z1);
        __half2 h23 = __floats2half2_rn(z2, z3);
        size_t zbase = (((size_t)(b * 32 + 4 * nt + tig)) << 12);
        zp[zbase + n]     = *(uint32_t*)&h01;
        zp[zbase + n + 8] = *(uint32_t*)&h23;
    }
}

// ---------------- driver -----------------------------------------------------
extern "C" void kernel_launch(void* const* d_in, const int* in_sizes, int n_in,
                              void* d_out, int out_size)
{
    const float* x       = (const float*)d_in[0];
    const float* conv1_w = (const float*)d_in[1];
    const float* bn1_g   = (const float*)d_in[2];
    const float* bn1_b   = (const float*)d_in[3];
    const float* theta_w = (const float*)d_in[4];
    const float* theta_b = (const float*)d_in[5];
    const float* phi_w   = (const float*)d_in[6];
    const float* phi_b   = (const float*)d_in[7];
    const float* g_w     = (const float*)d_in[8];
    const float* g_b     = (const float*)d_in[9];
    const float* W_w     = (const float*)d_in[10];
    const float* W_b     = (const float*)d_in[11];
    const float* conv2_w = (const float*)d_in[12];
    const float* bn2_g   = (const float*)d_in[13];
    const float* bn2_b   = (const float*)d_in[14];
    float* out = (float*)d_out;

    float* buf = nullptr;
    cudaGetSymbolAddress((void**)&buf, g_buf);
    float*    raw   = buf + OFF_RAW;
    uint32_t* th2   = (uint32_t*)(buf + OFF_TH2);
    uint32_t* ph2   = (uint32_t*)(buf + OFF_PH2);
    uint32_t* gp2   = (uint32_t*)(buf + OFF_GP2);
    uint32_t* x1p   = (uint32_t*)(buf + OFF_X1P);
    uint32_t* zp    = (uint32_t*)(buf + OFF_ZP);
    uint32_t* wpbuf = (uint32_t*)(buf + OFF_WP);
    float*    part1 = buf + OFF_PT1;
    float*    part2 = buf + OFF_PT2;

    cudaFuncSetAttribute(conv3x3_f16_kernel,
                         cudaFuncAttributeMaxDynamicSharedMemorySize, CONV_SMEM);

    // weight prep (5 conv sets + W1x1) + zero stats partials
    wtrans_f16_kernel<<<408, 256>>>(conv1_w, theta_w, phi_w, g_w, conv2_w, W_w,
                                    wpbuf, part1);

    // conv1 (fp32 input, fused BN stats) -> BN apply + ReLU + pack
    conv3x3_f16_kernel<<<dim3(32, 4, 1), 128, CONV_SMEM>>>(
        x, wpbuf, nullptr, nullptr, nullptr, raw, raw, raw, 0, 1, part1);
    bn_apply_relu_pack_kernel<<<2048, 256>>>(raw, part1, bn1_g, bn1_b, x1p);

    // theta (mode1), phi (mode2), g (mode3) in one launch
    conv3x3_f16_kernel<<<dim3(32, 4, 3), 128, CONV_SMEM>>>(
        x1p, wpbuf + 20480, theta_b, phi_b, g_b,
        th2, ph2, gp2, 1 | (2 << 8) | (3 << 16), 0, nullptr);

    // attention + fused 1x1 W conv + residual -> zp
    flash_fused_kernel<<<dim3(NN / 128, BB), 256>>>(
        th2, ph2, gp2, wpbuf + 102400, W_b, x, zp);

    // conv2 (fused BN stats) -> BN apply + ReLU -> out
    conv3x3_f16_kernel<<<dim3(32, 4, 1), 128, CONV_SMEM>>>(
        zp, wpbuf + 4 * 20480, nullptr, nullptr, nullptr, raw, raw, raw, 0, 0, part2);
    bn_apply_relu_kernel<<<1024, 256>>>((const float4*)raw, part2, bn2_g, bn2_b,
                                        (float4*)out);
}

// round 13
// speedup vs baseline: 2.2422x; 1.1743x over previous
#include <cuda_runtime.h>
#include <cuda_fp16.h>
#include <math.h>
#include <stdint.h>

#define CC 64
#define HH 64
#define WWD 64
#define NN 4096
#define BB 4

// ---------------- scratch (static device memory; no allocs allowed) ----------
__device__ float g_buf[8u * 1024u * 1024u];

static const size_t OFF_RAW = 0;                       // fp32 1M
static const size_t OFF_TH2 = 1u << 20;                // u32 [B,N,32] c-pairs
static const size_t OFF_PH2 = OFF_TH2 + (1u << 19);    // u32 [B,32,N] c-pairs
static const size_t OFF_GP2 = OFF_PH2 + (1u << 19);    // u32 [B,N/2,64] n-pairs
static const size_t OFF_X1P = OFF_GP2 + (1u << 19);    // u32 [B,32,N]
static const size_t OFF_ZP  = OFF_X1P + (1u << 19);
static const size_t OFF_WP  = OFF_ZP + (1u << 19);     // 5*20480 + 2048 u32
static const size_t OFF_PT1 = OFF_WP + 104448;         // 128 floats
static const size_t OFF_PT2 = OFF_PT1 + 128;

// ---------------- mma helpers --------------------------------------------------
__device__ __forceinline__ void mma_f16_k16(float c[4], const uint32_t a[4],
                                            uint32_t b0, uint32_t b1) {
    asm volatile(
        "mma.sync.aligned.m16n8k16.row.col.f32.f16.f16.f32 "
        "{%0,%1,%2,%3}, {%4,%5,%6,%7}, {%8,%9}, {%0,%1,%2,%3};"
        : "+f"(c[0]), "+f"(c[1]), "+f"(c[2]), "+f"(c[3])
        : "r"(a[0]), "r"(a[1]), "r"(a[2]), "r"(a[3]), "r"(b0), "r"(b1));
}

__device__ __forceinline__ void mma_f16_k8(float c[4], uint32_t a0, uint32_t a1,
                                           uint32_t b0) {
    asm volatile(
        "mma.sync.aligned.m16n8k8.row.col.f32.f16.f16.f32 "
        "{%0,%1,%2,%3}, {%4,%5}, {%6}, {%0,%1,%2,%3};"
        : "+f"(c[0]), "+f"(c[1]), "+f"(c[2]), "+f"(c[3])
        : "r"(a0), "r"(a1), "r"(b0));
}

// ---------------- weight prep: 5 conv sets + W1x1 + zero partials --------------
__global__ void wtrans_f16_kernel(
    const float* __restrict__ w0, const float* __restrict__ w1,
    const float* __restrict__ w2, const float* __restrict__ w3,
    const float* __restrict__ w4, const float* __restrict__ w1x1,
    uint32_t* __restrict__ wp, float* __restrict__ partz)
{
    if (blockIdx.x == 0 && threadIdx.x < 256) partz[threadIdx.x] = 0.f;
    int i = blockIdx.x * 256 + threadIdx.x;
    if (i >= 104448) return;
    if (i >= 102400) {
        int r = i - 102400;
        int kp = r >> 6, oc = r & 63;
        __half2 h = __floats2half2_rn(w1x1[oc * 64 + 2 * kp],
                                      w1x1[oc * 64 + 2 * kp + 1]);
        wp[i] = *(uint32_t*)&h;
        return;
    }
    int s  = i / 20480;
    int r  = i - s * 20480;
    int ch = r / 2560;
    int r2 = r - ch * 2560;
    int kp = r2 >> 6;
    int oc = r2 & 63;
    uint32_t outv = 0;
    if (kp < 36) {
        const float* w = (s == 0) ? w0 : (s == 1) ? w1 : (s == 2) ? w2 : (s == 3) ? w3 : w4;
        int tap = kp >> 2;
        int icp = kp & 3;
        int ic  = ch * 8 + icp * 2;
        __half2 h = __floats2half2_rn(w[oc * 576 + ic * 9 + tap],
                                      w[oc * 576 + (ic + 1) * 9 + tap]);
        outv = *(uint32_t*)&h;
    }
    wp[i] = outv;
}

// ---------------- 3x3 conv, fp16 tensor cores, 8 warps, 64x64 tiles -----------
// Block: 64 oc x 64 px (one image row). 8 warps: wh=w>>1 -> 16-oc group,
// wq=w&1 -> 32-px half. Grid (64, B, sets).
__global__ void __launch_bounds__(256) conv3x3_f16_kernel(
    const void* __restrict__ inRaw, const uint32_t* __restrict__ wp,
    const float* __restrict__ bias0, const float* __restrict__ bias1,
    const float* __restrict__ bias2,
    void* __restrict__ out0, void* __restrict__ out1, void* __restrict__ out2,
    int modes, int in_fp32, float* __restrict__ statsPart)
{
    extern __shared__ __align__(16) uint32_t smc[];
    uint32_t* Aw = smc;            // [40][72] = 2880 u32
    uint32_t* Is = smc + 2880;     // [icp=4][r=3][74], icp stride 232 (mod32=8)

    int s = blockIdx.z;
    const float* bias = (s == 0) ? bias0 : (s == 1) ? bias1 : bias2;
    void* out = (s == 0) ? out0 : (s == 1) ? out1 : out2;
    int mode = (modes >> (8 * s)) & 0xff;
    const uint32_t* wps = wp + (size_t)s * 20480;
    const uint32_t* inP = (const uint32_t*)inRaw;
    const float* inF = (const float*)inRaw;

    int b   = blockIdx.y;
    int y0  = blockIdx.x;          // output row
    int tid = threadIdx.x;
    int w    = tid >> 5;
    int lane = tid & 31;
    int gid  = lane >> 2;
    int tig  = lane & 3;
    int wh = w >> 1;               // oc group (16 oc)
    int wx = (w & 1) * 32;         // px half
    int colA = wh * 16 + gid;

    float c[4][4];                 // [nt][reg]
#pragma unroll
    for (int nt = 0; nt < 4; nt++)
#pragma unroll
        for (int r = 0; r < 4; r++) c[nt][r] = 0.f;

    for (int ch = 0; ch < 8; ch++) {
        __syncthreads();
        for (int i = tid; i < 2560; i += 256) {
            int kp = i >> 6, oc = i & 63;
            Aw[kp * 72 + oc] = wps[ch * 2560 + i];
        }
        // input: 4 icp x 3 rows x 66 cols
        for (int i = tid; i < 792; i += 256) {
            int icp = i / 198;
            int rem = i - icp * 198;
            int r   = rem / 66;
            int col = rem - r * 66;
            int gy = y0 + r - 1;
            int gx = col - 1;
            uint32_t v = 0;
            if (gy >= 0 && gy < HH && gx >= 0 && gx < WWD) {
                if (!in_fp32) {
                    v = inP[(((size_t)(b * 32 + ch * 4 + icp)) << 12) + (gy << 6) + gx];
                } else {
                    size_t fb = (((size_t)(b * CC + ch * 8 + 2 * icp)) << 12) + (gy << 6) + gx;
                    __half2 h = __floats2half2_rn(inF[fb], inF[fb + 4096]);
                    v = *(uint32_t*)&h;
                }
            }
            Is[icp * 232 + r * 74 + col] = v;
        }
        __syncthreads();

#pragma unroll
        for (int kk = 0; kk < 4; kk++) {
            const int t0 = 2 * kk, t1 = 2 * kk + 1;
            const int ky0 = t0 / 3, kx0 = t0 % 3;
            const int ky1 = t1 / 3, kx1 = t1 % 3;
            uint32_t a[4];
            a[0] = Aw[(8 * kk + tig) * 72 + colA];
            a[1] = Aw[(8 * kk + tig) * 72 + colA + 8];
            a[2] = Aw[(8 * kk + tig + 4) * 72 + colA];
            a[3] = Aw[(8 * kk + tig + 4) * 72 + colA + 8];
#pragma unroll
            for (int nt = 0; nt < 4; nt++) {
                int col = wx + 8 * nt + gid;
                uint32_t bf0 = Is[tig * 232 + ky0 * 74 + col + kx0];
                uint32_t bf1 = Is[tig * 232 + ky1 * 74 + col + kx1];
                mma_f16_k16(c[nt], a, bf0, bf1);
            }
        }
        {   // tap 8 (ky=2,kx=2), kp = 32+tig
            uint32_t a0 = Aw[(32 + tig) * 72 + colA];
            uint32_t a1 = Aw[(32 + tig) * 72 + colA + 8];
#pragma unroll
            for (int nt = 0; nt < 4; nt++) {
                uint32_t bf = Is[tig * 232 + 2 * 74 + wx + 8 * nt + gid + 2];
                mma_f16_k8(c[nt], a0, a1, bf);
            }
        }
    }

    // ---- epilogue: bias, stage [oc][64] pitch 66 fp32 ----
    __syncthreads();
    float* Os = (float*)smc;       // 64*66 = 4224 floats
    float bv0 = bias ? bias[colA] : 0.f;
    float bv1 = bias ? bias[colA + 8] : 0.f;
#pragma unroll
    for (int nt = 0; nt < 4; nt++) {
        int n = wx + nt * 8 + 2 * tig;
        float2 v0, v1;
        v0.x = c[nt][0] + bv0; v0.y = c[nt][1] + bv0;
        v1.x = c[nt][2] + bv1; v1.y = c[nt][3] + bv1;
        *(float2*)(Os + colA * 66 + n) = v0;
        *(float2*)(Os + (colA + 8) * 66 + n) = v1;
    }
    __syncthreads();
    int n0 = y0 * 64;
    if (mode == 0) {
        float* of = (float*)out;
        for (int i = tid; i < 4096; i += 256) {
            int oc = i >> 6, nl = i & 63;
            of[(((size_t)(b * CC + oc)) << 12) + n0 + nl] = Os[oc * 66 + nl];
        }
        if (statsPart) {
            int oc = tid >> 2, q = tid & 3;
            const float* row = Os + oc * 66 + q * 16;
            float s1 = 0.f, s2 = 0.f;
#pragma unroll
            for (int j = 0; j < 16; j++) {
                float v = row[j];
                s1 += v; s2 += v * v;
            }
            s1 += __shfl_xor_sync(0xffffffffu, s1, 1);
            s2 += __shfl_xor_sync(0xffffffffu, s2, 1);
            s1 += __shfl_xor_sync(0xffffffffu, s1, 2);
            s2 += __shfl_xor_sync(0xffffffffu, s2, 2);
            if (q == 0) {
                atomicAdd(statsPart + 2 * oc, s1);
                atomicAdd(statsPart + 2 * oc + 1, s2);
            }
        }
    } else if (mode == 1) {        // theta u32 [B,N,32]
        uint32_t* ou = (uint32_t*)out;
        for (int i = tid; i < 2048; i += 256) {
            int nl = i >> 5, ocp = i & 31;
            __half2 h = __floats2half2_rn(Os[2 * ocp * 66 + nl],
                                          Os[(2 * ocp + 1) * 66 + nl]);
            ou[((size_t)(b * NN + n0 + nl)) * 32 + ocp] = *(uint32_t*)&h;
        }
    } else if (mode == 2) {        // phi u32 [B,32,N]
        uint32_t* ou = (uint32_t*)out;
        for (int i = tid; i < 2048; i += 256) {
            int cp = i >> 6, nl = i & 63;
            __half2 h = __floats2half2_rn(Os[2 * cp * 66 + nl],
                                          Os[(2 * cp + 1) * 66 + nl]);
            ou[(((size_t)(b * 32 + cp)) << 12) + n0 + nl] = *(uint32_t*)&h;
        }
    } else {                       // g u32 [B,N/2,64]
        uint32_t* ou = (uint32_t*)out;
        for (int i = tid; i < 2048; i += 256) {
            int np = i >> 6, oc = i & 63;
            __half2 h = __floats2half2_rn(Os[oc * 66 + 2 * np],
                                          Os[oc * 66 + 2 * np + 1]);
            ou[((size_t)b * 2048 + (n0 >> 1) + np) * 64 + oc] = *(uint32_t*)&h;
        }
    }
}
#define CONV_SMEM (16896)

// helper: per-block recompute of scale/shift from fused partials
__device__ __forceinline__ void bn_make_scale_shift(
    const float* part, const float* gamma, const float* beta,
    float* sc_s, float* sf_s, int tid)
{
    if (tid < 64) {
        float s  = part[2 * tid];
        float s2 = part[2 * tid + 1];
        const float inv = 1.f / (float)(BB * NN);
        float mean = s * inv;
        float var  = s2 * inv - mean * mean;
        float r    = rsqrtf(var + 1e-5f);
        float sc   = gamma[tid] * r;
        sc_s[tid] = sc;
        sf_s[tid] = beta[tid] - mean * sc;
    }
    __syncthreads();
}

__global__ void bn_apply_relu_kernel(const float4* __restrict__ in,
                                     const float* __restrict__ part,
                                     const float* __restrict__ gamma,
                                     const float* __restrict__ beta,
                                     float4* __restrict__ out)
{
    __shared__ float sc_s[64], sf_s[64];
    bn_make_scale_shift(part, gamma, beta, sc_s, sf_s, threadIdx.x);
    int i = blockIdx.x * 256 + threadIdx.x;
    int c = (i >> 10) & 63;
    float sc = sc_s[c], sf = sf_s[c];
    float4 v = in[i];
    v.x = fmaxf(fmaf(v.x, sc, sf), 0.f);
    v.y = fmaxf(fmaf(v.y, sc, sf), 0.f);
    v.z = fmaxf(fmaf(v.z, sc, sf), 0.f);
    v.w = fmaxf(fmaf(v.w, sc, sf), 0.f);
    out[i] = v;
}

__global__ void bn_apply_relu_pack_kernel(const float* __restrict__ in,
                                          const float* __restrict__ part,
                                          const float* __restrict__ gamma,
                                          const float* __restrict__ beta,
                                          uint32_t* __restrict__ outp)
{
    __shared__ float sc_s[64], sf_s[64];
    bn_make_scale_shift(part, gamma, beta, sc_s, sf_s, threadIdx.x);
    int i = blockIdx.x * 256 + threadIdx.x;
    int b  = i >> 17;
    int cp = (i >> 12) & 31;
    int n  = i & 4095;
    size_t base = (((size_t)(b * CC + 2 * cp)) << 12) + n;
    float v0 = fmaxf(fmaf(in[base],        sc_s[2 * cp],     sf_s[2 * cp]),     0.f);
    float v1 = fmaxf(fmaf(in[base + 4096], sc_s[2 * cp + 1], sf_s[2 * cp + 1]), 0.f);
    __half2 h = __floats2half2_rn(v0, v1);
    outp[i] = *(uint32_t*)&h;
}

// ---------------- flash attention Br=128, double-buffered K/G, fused W --------
// dyn smem: KG[2][4608] (K 2304 + G 2304 each), Ps 4608 -> 13824 u32 = 55296 B
__global__ void __launch_bounds__(256) flash_fused_kernel(
    const uint32_t* __restrict__ Qt2, const uint32_t* __restrict__ Kp,
    const uint32_t* __restrict__ Gp, const uint32_t* __restrict__ W1p,
    const float* __restrict__ W1b, const float* __restrict__ x,
    uint32_t* __restrict__ zp)
{
    extern __shared__ __align__(16) uint32_t KG[];
    uint32_t* Ps = KG + 9216;

    int b   = blockIdx.y;
    int n0  = blockIdx.x * 128;
    int tid = threadIdx.x;
    int w    = tid >> 5;
    int lane = tid & 31;
    int gid  = lane >> 2;
    int tig  = lane & 3;
    uint32_t* Pw = Ps + w * 576;

    uint32_t aq[4][4];
    {
        const uint32_t* qb2 = Qt2 + ((size_t)(b * NN + n0 + w * 16)) * 32;
#pragma unroll
        for (int kk = 0; kk < 4; kk++) {
            aq[kk][0] = qb2[gid * 32 + 8 * kk + tig];
            aq[kk][1] = qb2[(gid + 8) * 32 + 8 * kk + tig];
            aq[kk][2] = qb2[gid * 32 + 8 * kk + tig + 4];
            aq[kk][3] = qb2[(gid + 8) * 32 + 8 * kk + tig + 4];
        }
    }

    float o[8][4];
#pragma unroll
    for (int nt = 0; nt < 8; nt++)
#pragma unroll
        for (int r = 0; r < 4; r++) o[nt][r] = 0.f;
    float rm0 = -1e30f, rm1 = -1e30f, rl0 = 0.f, rl1 = 0.f;

    // prefetch coords (uint4 granularity): 512 uint4 per 2048-u32 tile
    int pr_row[2], pr_m4[2];
#pragma unroll
    for (int r = 0; r < 2; r++) {
        int i4 = tid + 256 * r;
        pr_row[r] = i4 >> 4;
        pr_m4[r]  = (i4 & 15) << 2;
    }

    // ---- prologue: load tile 0 into buffer 0 ----
#pragma unroll
    for (int r = 0; r < 2; r++) {
        uint4 kv = *(const uint4*)(Kp + (((size_t)(b * 32 + pr_row[r])) << 12) + pr_m4[r]);
        uint4 gv = *(const uint4*)(Gp + ((size_t)b * 2048 + pr_row[r]) * 64 + pr_m4[r]);
        *(uint4*)(KG + pr_row[r] * 72 + pr_m4[r]) = kv;
        *(uint4*)(KG + 2304 + pr_row[r] * 72 + pr_m4[r]) = gv;
    }
    __syncthreads();

    for (int jt = 0; jt < 64; jt++) {
        const uint32_t* Ks2 = KG + (jt & 1) * 4608;
        const uint32_t* Gs2 = Ks2 + 2304;

        // issue prefetch LDGs for next tile
        uint4 pk[2], pg[2];
        bool pre = (jt + 1) < 64;
        if (pre) {
            int jn = (jt + 1) * 64;
#pragma unroll
            for (int r = 0; r < 2; r++) {
                pk[r] = *(const uint4*)(Kp + (((size_t)(b * 32 + pr_row[r])) << 12) + jn + pr_m4[r]);
                pg[r] = *(const uint4*)(Gp + ((size_t)b * 2048 + (jn >> 1) + pr_row[r]) * 64 + pr_m4[r]);
            }
        }

        // ---- S = Q K ----
        float s[8][4];
#pragma unroll
        for (int nt = 0; nt < 8; nt++)
#pragma unroll
            for (int r = 0; r < 4; r++) s[nt][r] = 0.f;
#pragma unroll
        for (int kk = 0; kk < 4; kk++) {
            const uint32_t* kr0 = Ks2 + (8 * kk + tig) * 72 + gid;
            const uint32_t* kr1 = Ks2 + (8 * kk + tig + 4) * 72 + gid;
#pragma unroll
            for (int nt = 0; nt < 8; nt++)
                mma_f16_k16(s[nt], aq[kk], kr0[8 * nt], kr1[8 * nt]);
        }

        // ---- online softmax ----
        float mx0 = -1e30f, mx1 = -1e30f;
#pragma unroll
        for (int nt = 0; nt < 8; nt++) {
            mx0 = fmaxf(mx0, fmaxf(s[nt][0], s[nt][1]));
            mx1 = fmaxf(mx1, fmaxf(s[nt][2], s[nt][3]));
        }
        mx0 = fmaxf(mx0, __shfl_xor_sync(0xffffffffu, mx0, 1));
        mx0 = fmaxf(mx0, __shfl_xor_sync(0xffffffffu, mx0, 2));
        mx1 = fmaxf(mx1, __shfl_xor_sync(0xffffffffu, mx1, 1));
        mx1 = fmaxf(mx1, __shfl_xor_sync(0xffffffffu, mx1, 2));

        float mn0 = fmaxf(rm0, mx0), mn1 = fmaxf(rm1, mx1);
        float al0 = __expf(rm0 - mn0), al1 = __expf(rm1 - mn1);
        rm0 = mn0; rm1 = mn1;

        float rs0 = 0.f, rs1 = 0.f;
#pragma unroll
        for (int nt = 0; nt < 8; nt++) {
            float p0 = __expf(s[nt][0] - mn0);
            float p1 = __expf(s[nt][1] - mn0);
            float p2 = __expf(s[nt][2] - mn1);
            float p3 = __expf(s[nt][3] - mn1);
            rs0 += p0 + p1; rs1 += p2 + p3;
            __half2 h01 = __floats2half2_rn(p0, p1);
            __half2 h23 = __floats2half2_rn(p2, p3);
            Pw[gid * 36 + 4 * nt + tig] = *(uint32_t*)&h01;
            Pw[(gid + 8) * 36 + 4 * nt + tig] = *(uint32_t*)&h23;
        }
        rs0 += __shfl_xor_sync(0xffffffffu, rs0, 1);
        rs0 += __shfl_xor_sync(0xffffffffu, rs0, 2);
        rs1 += __shfl_xor_sync(0xffffffffu, rs1, 1);
        rs1 += __shfl_xor_sync(0xffffffffu, rs1, 2);
        rl0 = rl0 * al0 + rs0;
        rl1 = rl1 * al1 + rs1;

#pragma unroll
        for (int nt = 0; nt < 8; nt++) {
            o[nt][0] *= al0; o[nt][1] *= al0;
            o[nt][2] *= al1; o[nt][3] *= al1;
        }
        __syncwarp();

        // ---- O += P G ----
#pragma unroll
        for (int kk = 0; kk < 4; kk++) {
            uint32_t pa[4];
            pa[0] = Pw[gid * 36 + 8 * kk + tig];
            pa[1] = Pw[(gid + 8) * 36 + 8 * kk + tig];
            pa[2] = Pw[gid * 36 + 8 * kk + tig + 4];
            pa[3] = Pw[(gid + 8) * 36 + 8 * kk + tig + 4];
            const uint32_t* gr0 = Gs2 + (8 * kk + tig) * 72 + gid;
            const uint32_t* gr1 = Gs2 + (8 * kk + tig + 4) * 72 + gid;
#pragma unroll
            for (int nt = 0; nt < 8; nt++)
                mma_f16_k16(o[nt], pa, gr0[8 * nt], gr1[8 * nt]);
        }

        // ---- write prefetched tile into alternate buffer ----
        if (pre) {
            uint32_t* nK = KG + ((jt + 1) & 1) * 4608;
#pragma unroll
            for (int r = 0; r < 2; r++) {
                *(uint4*)(nK + pr_row[r] * 72 + pr_m4[r]) = pk[r];
                *(uint4*)(nK + 2304 + pr_row[r] * 72 + pr_m4[r]) = pg[r];
            }
        }
        __syncthreads();
    }

    // ---- fused epilogue: y as half2 c-pairs; z = W*y + Wb + x ----
    float li0 = 1.f / rl0, li1 = 1.f / rl1;
    uint32_t* Ys = Ps;
#pragma unroll
    for (int nt = 0; nt < 8; nt++) {
        __half2 h01 = __floats2half2_rn(o[nt][0] * li0, o[nt][1] * li0);
        __half2 h23 = __floats2half2_rn(o[nt][2] * li1, o[nt][3] * li1);
        Ys[(w * 16 + gid) * 36 + 4 * nt + tig] = *(uint32_t*)&h01;
        Ys[(w * 16 + gid + 8) * 36 + 4 * nt + tig] = *(uint32_t*)&h23;
    }
    for (int i = tid; i < 2048; i += 256) {
        int kp = i >> 6, oc = i & 63;
        KG[kp * 72 + oc] = W1p[i];
    }
    __syncthreads();

    float d[8][4];
#pragma unroll
    for (int nt = 0; nt < 8; nt++)
#pragma unroll
        for (int r = 0; r < 4; r++) d[nt][r] = 0.f;
#pragma unroll
    for (int kk = 0; kk < 4; kk++) {
        uint32_t pa[4];
        pa[0] = Ys[(w * 16 + gid) * 36 + 8 * kk + tig];
        pa[1] = Ys[(w * 16 + gid + 8) * 36 + 8 * kk + tig];
        pa[2] = Ys[(w * 16 + gid) * 36 + 8 * kk + tig + 4];
        pa[3] = Ys[(w * 16 + gid + 8) * 36 + 8 * kk + tig + 4];
        const uint32_t* wr0 = KG + (8 * kk + tig) * 72 + gid;
        const uint32_t* wr1 = KG + (8 * kk + tig + 4) * 72 + gid;
#pragma unroll
        for (int nt = 0; nt < 8; nt++)
            mma_f16_k16(d[nt], pa, wr0[8 * nt], wr1[8 * nt]);
    }

#pragma unroll
    for (int nt = 0; nt < 8; nt++) {
        int oc0 = 8 * nt + 2 * tig;
        float b0 = W1b[oc0], b1 = W1b[oc0 + 1];
        int n  = n0 + w * 16 + gid;
        size_t x0 = (((size_t)(b * CC + oc0)) << 12);
        float z0 = d[nt][0] + b0 + x[x0 + n];
        float z1 = d[nt][1] + b1 + x[x0 + 4096 + n];
        float z2 = d[nt][2] + b0 + x[x0 + n + 8];
        float z3 = d[nt][3] + b1 + x[x0 + 4096 + n + 8];
        __half2 h01 = __floats2half2_rn(z0, z1);
        __half2 h23 = __floats2half2_rn(z2, z3);
        size_t zbase = (((size_t)(b * 32 + 4 * nt + tig)) << 12);
        zp[zbase + n]     = *(uint32_t*)&h01;
        zp[zbase + n + 8] = *(uint32_t*)&h23;
    }
}
#define FLASH_SMEM (55296)

// ---------------- driver -----------------------------------------------------
extern "C" void kernel_launch(void* const* d_in, const int* in_sizes, int n_in,
                              void* d_out, int out_size)
{
    const float* x       = (const float*)d_in[0];
    const float* conv1_w = (const float*)d_in[1];
    const float* bn1_g   = (const float*)d_in[2];
    const float* bn1_b   = (const float*)d_in[3];
    const float* theta_w = (const float*)d_in[4];
    const float* theta_b = (const float*)d_in[5];
    const float* phi_w   = (const float*)d_in[6];
    const float* phi_b   = (const float*)d_in[7];
    const float* g_w     = (const float*)d_in[8];
    const float* g_b     = (const float*)d_in[9];
    const float* W_w     = (const float*)d_in[10];
    const float* W_b     = (const float*)d_in[11];
    const float* conv2_w = (const float*)d_in[12];
    const float* bn2_g   = (const float*)d_in[13];
    const float* bn2_b   = (const float*)d_in[14];
    float* out = (float*)d_out;

    float* buf = nullptr;
    cudaGetSymbolAddress((void**)&buf, g_buf);
    float*    raw   = buf + OFF_RAW;
    uint32_t* th2   = (uint32_t*)(buf + OFF_TH2);
    uint32_t* ph2   = (uint32_t*)(buf + OFF_PH2);
    uint32_t* gp2   = (uint32_t*)(buf + OFF_GP2);
    uint32_t* x1p   = (uint32_t*)(buf + OFF_X1P);
    uint32_t* zp    = (uint32_t*)(buf + OFF_ZP);
    uint32_t* wpbuf = (uint32_t*)(buf + OFF_WP);
    float*    part1 = buf + OFF_PT1;
    float*    part2 = buf + OFF_PT2;

    cudaFuncSetAttribute(conv3x3_f16_kernel,
                         cudaFuncAttributeMaxDynamicSharedMemorySize, CONV_SMEM);
    cudaFuncSetAttribute(flash_fused_kernel,
                         cudaFuncAttributeMaxDynamicSharedMemorySize, FLASH_SMEM);

    // weight prep (5 conv sets + W1x1) + zero stats partials
    wtrans_f16_kernel<<<408, 256>>>(conv1_w, theta_w, phi_w, g_w, conv2_w, W_w,
                                    wpbuf, part1);

    // conv1 (fp32 input, fused BN stats) -> BN apply + ReLU + pack
    conv3x3_f16_kernel<<<dim3(64, BB, 1), 256, CONV_SMEM>>>(
        x, wpbuf, nullptr, nullptr, nullptr, raw, raw, raw, 0, 1, part1);
    bn_apply_relu_pack_kernel<<<2048, 256>>>(raw, part1, bn1_g, bn1_b, x1p);

    // theta (mode1), phi (mode2), g (mode3) in one launch
    conv3x3_f16_kernel<<<dim3(64, BB, 3), 256, CONV_SMEM>>>(
        x1p, wpbuf + 20480, theta_b, phi_b, g_b,
        th2, ph2, gp2, 1 | (2 << 8) | (3 << 16), 0, nullptr);

    // attention + fused 1x1 W conv + residual -> zp
    flash_fused_kernel<<<dim3(NN / 128, BB), 256, FLASH_SMEM>>>(
        th2, ph2, gp2, wpbuf + 102400, W_b, x, zp);

    // conv2 (fused BN stats) -> BN apply + ReLU -> out
    conv3x3_f16_kernel<<<dim3(64, BB, 1), 256, CONV_SMEM>>>(
        zp, wpbuf + 4 * 20480, nullptr, nullptr, nullptr, raw, raw, raw, 0, 0, part2);
    bn_apply_relu_kernel<<<1024, 256>>>((const float4*)raw, part2, bn2_g, bn2_b,
                                        (float4*)out);
}

// round 14
// speedup vs baseline: 2.2727x; 1.0136x over previous
#include <cuda_runtime.h>
#include <cuda_fp16.h>
#include <math.h>
#include <stdint.h>

#define CC 64
#define HH 64
#define WWD 64
#define NN 4096
#define BB 4

// ---------------- scratch (static device memory; no allocs allowed) ----------
__device__ float g_buf[8u * 1024u * 1024u];

static const size_t OFF_RAW = 0;                       // fp32 1M
static const size_t OFF_TH2 = 1u << 20;                // u32 [B,N,32] c-pairs
static const size_t OFF_PH2 = OFF_TH2 + (1u << 19);    // u32 [B,32,N] c-pairs
static const size_t OFF_GP2 = OFF_PH2 + (1u << 19);    // u32 [B,N/2,64] n-pairs
static const size_t OFF_X1P = OFF_GP2 + (1u << 19);    // u32 [B,32,N]
static const size_t OFF_ZP  = OFF_X1P + (1u << 19);
static const size_t OFF_WP  = OFF_ZP + (1u << 19);     // 5*20480 + 2048 u32
static const size_t OFF_PT1 = OFF_WP + 104448;         // 128 floats
static const size_t OFF_PT2 = OFF_PT1 + 128;

// ---------------- mma helpers --------------------------------------------------
__device__ __forceinline__ void mma_f16_k16(float c[4], const uint32_t a[4],
                                            uint32_t b0, uint32_t b1) {
    asm volatile(
        "mma.sync.aligned.m16n8k16.row.col.f32.f16.f16.f32 "
        "{%0,%1,%2,%3}, {%4,%5,%6,%7}, {%8,%9}, {%0,%1,%2,%3};"
        : "+f"(c[0]), "+f"(c[1]), "+f"(c[2]), "+f"(c[3])
        : "r"(a[0]), "r"(a[1]), "r"(a[2]), "r"(a[3]), "r"(b0), "r"(b1));
}

__device__ __forceinline__ void mma_f16_k8(float c[4], uint32_t a0, uint32_t a1,
                                           uint32_t b0) {
    asm volatile(
        "mma.sync.aligned.m16n8k8.row.col.f32.f16.f16.f32 "
        "{%0,%1,%2,%3}, {%4,%5}, {%6}, {%0,%1,%2,%3};"
        : "+f"(c[0]), "+f"(c[1]), "+f"(c[2]), "+f"(c[3])
        : "r"(a0), "r"(a1), "r"(b0));
}

// ---------------- weight prep: 5 conv sets + W1x1 + zero partials --------------
__global__ void wtrans_f16_kernel(
    const float* __restrict__ w0, const float* __restrict__ w1,
    const float* __restrict__ w2, const float* __restrict__ w3,
    const float* __restrict__ w4, const float* __restrict__ w1x1,
    uint32_t* __restrict__ wp, float* __restrict__ partz)
{
    if (blockIdx.x == 0 && threadIdx.x < 256) partz[threadIdx.x] = 0.f;
    int i = blockIdx.x * 256 + threadIdx.x;
    if (i >= 104448) return;
    if (i >= 102400) {
        int r = i - 102400;
        int kp = r >> 6, oc = r & 63;
        __half2 h = __floats2half2_rn(w1x1[oc * 64 + 2 * kp],
                                      w1x1[oc * 64 + 2 * kp + 1]);
        wp[i] = *(uint32_t*)&h;
        return;
    }
    int s  = i / 20480;
    int r  = i - s * 20480;
    int ch = r / 2560;
    int r2 = r - ch * 2560;
    int kp = r2 >> 6;
    int oc = r2 & 63;
    uint32_t outv = 0;
    if (kp < 36) {
        const float* w = (s == 0) ? w0 : (s == 1) ? w1 : (s == 2) ? w2 : (s == 3) ? w3 : w4;
        int tap = kp >> 2;
        int icp = kp & 3;
        int ic  = ch * 8 + icp * 2;
        __half2 h = __floats2half2_rn(w[oc * 576 + ic * 9 + tap],
                                      w[oc * 576 + (ic + 1) * 9 + tap]);
        outv = *(uint32_t*)&h;
    }
    wp[i] = outv;
}

// ---------------- 3x3 conv, fp16 tensor cores, 8 warps, 64oc x 128px ----------
// Warp tile 32oc x 32px (2mt x 4nt): wo=w&1 oc-half, wq=w>>1 px-quarter
// (wy=wq>>1 row, wx=(wq&1)*32). Grid (32, B, sets).
__global__ void __launch_bounds__(256) conv3x3_f16_kernel(
    const void* __restrict__ inRaw, const uint32_t* __restrict__ wp,
    const float* __restrict__ bias0, const float* __restrict__ bias1,
    const float* __restrict__ bias2,
    void* __restrict__ out0, void* __restrict__ out1, void* __restrict__ out2,
    int modes, int in_fp32, float* __restrict__ statsPart)
{
    extern __shared__ __align__(16) uint32_t smc[];
    uint32_t* Aw = smc;            // [40][72] = 2880 u32
    uint32_t* Is = smc + 2880;     // [icp=4][r=4][74], icp stride 296

    int s = blockIdx.z;
    const float* bias = (s == 0) ? bias0 : (s == 1) ? bias1 : bias2;
    void* out = (s == 0) ? out0 : (s == 1) ? out1 : out2;
    int mode = (modes >> (8 * s)) & 0xff;
    const uint32_t* wps = wp + (size_t)s * 20480;
    const uint32_t* inP = (const uint32_t*)inRaw;
    const float* inF = (const float*)inRaw;

    int b   = blockIdx.y;
    int y0  = blockIdx.x * 2;
    int tid = threadIdx.x;
    int w    = tid >> 5;
    int lane = tid & 31;
    int gid  = lane >> 2;
    int tig  = lane & 3;
    int wo = w & 1;                // oc half (32 oc)
    int wq = w >> 1;               // px quarter
    int wy = wq >> 1;              // output row within pair
    int wx = (wq & 1) * 32;        // x offset

    float c[2][4][4];              // [mt][nt][reg]
#pragma unroll
    for (int mt = 0; mt < 2; mt++)
#pragma unroll
        for (int nt = 0; nt < 4; nt++)
#pragma unroll
            for (int r = 0; r < 4; r++) c[mt][nt][r] = 0.f;

    for (int ch = 0; ch < 8; ch++) {
        __syncthreads();
        for (int i = tid; i < 2560; i += 256) {
            int kp = i >> 6, oc = i & 63;
            Aw[kp * 72 + oc] = wps[ch * 2560 + i];
        }
        // input: 4 icp x 4 rows x 66 cols
        for (int i = tid; i < 1056; i += 256) {
            int icp = i / 264;
            int rem = i - icp * 264;
            int r   = rem / 66;
            int col = rem - r * 66;
            int gy = y0 + r - 1;
            int gx = col - 1;
            uint32_t v = 0;
            if (gy >= 0 && gy < HH && gx >= 0 && gx < WWD) {
                if (!in_fp32) {
                    v = inP[(((size_t)(b * 32 + ch * 4 + icp)) << 12) + (gy << 6) + gx];
                } else {
                    size_t fb = (((size_t)(b * CC + ch * 8 + 2 * icp)) << 12) + (gy << 6) + gx;
                    __half2 h = __floats2half2_rn(inF[fb], inF[fb + 4096]);
                    v = *(uint32_t*)&h;
                }
            }
            Is[icp * 296 + r * 74 + col] = v;
        }
        __syncthreads();

#pragma unroll
        for (int kk = 0; kk < 4; kk++) {
            const int t0 = 2 * kk, t1 = 2 * kk + 1;
            const int ky0 = t0 / 3, kx0 = t0 % 3;
            const int ky1 = t1 / 3, kx1 = t1 % 3;
            uint32_t a[2][4];
#pragma unroll
            for (int mt = 0; mt < 2; mt++) {
                int colA = wo * 32 + mt * 16 + gid;
                a[mt][0] = Aw[(8 * kk + tig) * 72 + colA];
                a[mt][1] = Aw[(8 * kk + tig) * 72 + colA + 8];
                a[mt][2] = Aw[(8 * kk + tig + 4) * 72 + colA];
                a[mt][3] = Aw[(8 * kk + tig + 4) * 72 + colA + 8];
            }
#pragma unroll
            for (int nt = 0; nt < 4; nt++) {
                int col = wx + 8 * nt + gid;
                uint32_t bf0 = Is[tig * 296 + (wy + ky0) * 74 + col + kx0];
                uint32_t bf1 = Is[tig * 296 + (wy + ky1) * 74 + col + kx1];
#pragma unroll
                for (int mt = 0; mt < 2; mt++)
                    mma_f16_k16(c[mt][nt], a[mt], bf0, bf1);
            }
        }
        {   // tap 8 (ky=2,kx=2), kp = 32+tig
            uint32_t a0[2], a1[2];
#pragma unroll
            for (int mt = 0; mt < 2; mt++) {
                int colA = wo * 32 + mt * 16 + gid;
                a0[mt] = Aw[(32 + tig) * 72 + colA];
                a1[mt] = Aw[(32 + tig) * 72 + colA + 8];
            }
#pragma unroll
            for (int nt = 0; nt < 4; nt++) {
                uint32_t bf = Is[tig * 296 + (wy + 2) * 74 + wx + 8 * nt + gid + 2];
#pragma unroll
                for (int mt = 0; mt < 2; mt++)
                    mma_f16_k8(c[mt][nt], a0[mt], a1[mt], bf);
            }
        }
    }

    // ---- epilogue: bias, stage [oc][128] pitch 130 fp32 ----
    __syncthreads();
    float* Os = (float*)smc;       // 64*130 floats
#pragma unroll
    for (int mt = 0; mt < 2; mt++) {
        int colA = wo * 32 + mt * 16 + gid;
        float bv0 = bias ? bias[colA] : 0.f;
        float bv1 = bias ? bias[colA + 8] : 0.f;
#pragma unroll
        for (int nt = 0; nt < 4; nt++) {
            int n = wx + wy * 64 + nt * 8 + 2 * tig;
            float2 v0, v1;
            v0.x = c[mt][nt][0] + bv0; v0.y = c[mt][nt][1] + bv0;
            v1.x = c[mt][nt][2] + bv1; v1.y = c[mt][nt][3] + bv1;
            *(float2*)(Os + colA * 130 + n) = v0;
            *(float2*)(Os + (colA + 8) * 130 + n) = v1;
        }
    }
    __syncthreads();
    int n0 = blockIdx.x * 128;
    if (mode == 0) {
        float* of = (float*)out;
        for (int i = tid; i < 8192; i += 256) {
            int oc = i >> 7, nl = i & 127;
            of[(((size_t)(b * CC + oc)) << 12) + n0 + nl] = Os[oc * 130 + nl];
        }
        if (statsPart) {
            int oc = tid >> 2, q = tid & 3;
            const float* row = Os + oc * 130 + q * 32;
            float s1 = 0.f, s2 = 0.f;
#pragma unroll
            for (int j = 0; j < 32; j++) {
                float v = row[j];
                s1 += v; s2 += v * v;
            }
            s1 += __shfl_xor_sync(0xffffffffu, s1, 1);
            s2 += __shfl_xor_sync(0xffffffffu, s2, 1);
            s1 += __shfl_xor_sync(0xffffffffu, s1, 2);
            s2 += __shfl_xor_sync(0xffffffffu, s2, 2);
            if (q == 0) {
                atomicAdd(statsPart + 2 * oc, s1);
                atomicAdd(statsPart + 2 * oc + 1, s2);
            }
        }
    } else if (mode == 1) {        // theta u32 [B,N,32]
        uint32_t* ou = (uint32_t*)out;
        for (int i = tid; i < 4096; i += 256) {
            int nl = i >> 5, ocp = i & 31;
            __half2 h = __floats2half2_rn(Os[2 * ocp * 130 + nl],
                                          Os[(2 * ocp + 1) * 130 + nl]);
            ou[((size_t)(b * NN + n0 + nl)) * 32 + ocp] = *(uint32_t*)&h;
        }
    } else if (mode == 2) {        // phi u32 [B,32,N]
        uint32_t* ou = (uint32_t*)out;
        for (int i = tid; i < 4096; i += 256) {
            int cp = i >> 7, nl = i & 127;
            __half2 h = __floats2half2_rn(Os[2 * cp * 130 + nl],
                                          Os[(2 * cp + 1) * 130 + nl]);
            ou[(((size_t)(b * 32 + cp)) << 12) + n0 + nl] = *(uint32_t*)&h;
        }
    } else {                       // g u32 [B,N/2,64]
        uint32_t* ou = (uint32_t*)out;
        for (int i = tid; i < 4096; i += 256) {
            int np = i >> 6, oc = i & 63;
            __half2 h = __floats2half2_rn(Os[oc * 130 + 2 * np],
                                          Os[oc * 130 + 2 * np + 1]);
            ou[((size_t)b * 2048 + (n0 >> 1) + np) * 64 + oc] = *(uint32_t*)&h;
        }
    }
}
#define CONV_SMEM (33280)

// helper: per-block recompute of scale/shift from fused partials
__device__ __forceinline__ void bn_make_scale_shift(
    const float* part, const float* gamma, const float* beta,
    float* sc_s, float* sf_s, int tid)
{
    if (tid < 64) {
        float s  = part[2 * tid];
        float s2 = part[2 * tid + 1];
        const float inv = 1.f / (float)(BB * NN);
        float mean = s * inv;
        float var  = s2 * inv - mean * mean;
        float r    = rsqrtf(var + 1e-5f);
        float sc   = gamma[tid] * r;
        sc_s[tid] = sc;
        sf_s[tid] = beta[tid] - mean * sc;
    }
    __syncthreads();
}

__global__ void bn_apply_relu_kernel(const float4* __restrict__ in,
                                     const float* __restrict__ part,
                                     const float* __restrict__ gamma,
                                     const float* __restrict__ beta,
                                     float4* __restrict__ out)
{
    __shared__ float sc_s[64], sf_s[64];
    bn_make_scale_shift(part, gamma, beta, sc_s, sf_s, threadIdx.x);
    int i = blockIdx.x * 256 + threadIdx.x;
    int c = (i >> 10) & 63;
    float sc = sc_s[c], sf = sf_s[c];
    float4 v = in[i];
    v.x = fmaxf(fmaf(v.x, sc, sf), 0.f);
    v.y = fmaxf(fmaf(v.y, sc, sf), 0.f);
    v.z = fmaxf(fmaf(v.z, sc, sf), 0.f);
    v.w = fmaxf(fmaf(v.w, sc, sf), 0.f);
    out[i] = v;
}

__global__ void bn_apply_relu_pack_kernel(const float* __restrict__ in,
                                          const float* __restrict__ part,
                                          const float* __restrict__ gamma,
                                          const float* __restrict__ beta,
                                          uint32_t* __restrict__ outp)
{
    __shared__ float sc_s[64], sf_s[64];
    bn_make_scale_shift(part, gamma, beta, sc_s, sf_s, threadIdx.x);
    int i = blockIdx.x * 256 + threadIdx.x;
    int b  = i >> 17;
    int cp = (i >> 12) & 31;
    int n  = i & 4095;
    size_t base = (((size_t)(b * CC + 2 * cp)) << 12) + n;
    float v0 = fmaxf(fmaf(in[base],        sc_s[2 * cp],     sf_s[2 * cp]),     0.f);
    float v1 = fmaxf(fmaf(in[base + 4096], sc_s[2 * cp + 1], sf_s[2 * cp + 1]), 0.f);
    __half2 h = __floats2half2_rn(v0, v1);
    outp[i] = *(uint32_t*)&h;
}

// ---------------- flash attention Br=128, double-buffered K/G, fused W --------
__global__ void __launch_bounds__(256) flash_fused_kernel(
    const uint32_t* __restrict__ Qt2, const uint32_t* __restrict__ Kp,
    const uint32_t* __restrict__ Gp, const uint32_t* __restrict__ W1p,
    const float* __restrict__ W1b, const float* __restrict__ x,
    uint32_t* __restrict__ zp)
{
    extern __shared__ __align__(16) uint32_t KG[];
    uint32_t* Ps = KG + 9216;

    int b   = blockIdx.y;
    int n0  = blockIdx.x * 128;
    int tid = threadIdx.x;
    int w    = tid >> 5;
    int lane = tid & 31;
    int gid  = lane >> 2;
    int tig  = lane & 3;
    uint32_t* Pw = Ps + w * 576;

    uint32_t aq[4][4];
    {
        const uint32_t* qb2 = Qt2 + ((size_t)(b * NN + n0 + w * 16)) * 32;
#pragma unroll
        for (int kk = 0; kk < 4; kk++) {
            aq[kk][0] = qb2[gid * 32 + 8 * kk + tig];
            aq[kk][1] = qb2[(gid + 8) * 32 + 8 * kk + tig];
            aq[kk][2] = qb2[gid * 32 + 8 * kk + tig + 4];
            aq[kk][3] = qb2[(gid + 8) * 32 + 8 * kk + tig + 4];
        }
    }

    float o[8][4];
#pragma unroll
    for (int nt = 0; nt < 8; nt++)
#pragma unroll
        for (int r = 0; r < 4; r++) o[nt][r] = 0.f;
    float rm0 = -1e30f, rm1 = -1e30f, rl0 = 0.f, rl1 = 0.f;

    int pr_row[2], pr_m4[2];
#pragma unroll
    for (int r = 0; r < 2; r++) {
        int i4 = tid + 256 * r;
        pr_row[r] = i4 >> 4;
        pr_m4[r]  = (i4 & 15) << 2;
    }

#pragma unroll
    for (int r = 0; r < 2; r++) {
        uint4 kv = *(const uint4*)(Kp + (((size_t)(b * 32 + pr_row[r])) << 12) + pr_m4[r]);
        uint4 gv = *(const uint4*)(Gp + ((size_t)b * 2048 + pr_row[r]) * 64 + pr_m4[r]);
        *(uint4*)(KG + pr_row[r] * 72 + pr_m4[r]) = kv;
        *(uint4*)(KG + 2304 + pr_row[r] * 72 + pr_m4[r]) = gv;
    }
    __syncthreads();

    for (int jt = 0; jt < 64; jt++) {
        const uint32_t* Ks2 = KG + (jt & 1) * 4608;
        const uint32_t* Gs2 = Ks2 + 2304;

        uint4 pk[2], pg[2];
        bool pre = (jt + 1) < 64;
        if (pre) {
            int jn = (jt + 1) * 64;
#pragma unroll
            for (int r = 0; r < 2; r++) {
                pk[r] = *(const uint4*)(Kp + (((size_t)(b * 32 + pr_row[r])) << 12) + jn + pr_m4[r]);
                pg[r] = *(const uint4*)(Gp + ((size_t)b * 2048 + (jn >> 1) + pr_row[r]) * 64 + pr_m4[r]);
            }
        }

        float s[8][4];
#pragma unroll
        for (int nt = 0; nt < 8; nt++)
#pragma unroll
            for (int r = 0; r < 4; r++) s[nt][r] = 0.f;
#pragma unroll
        for (int kk = 0; kk < 4; kk++) {
            const uint32_t* kr0 = Ks2 + (8 * kk + tig) * 72 + gid;
            const uint32_t* kr1 = Ks2 + (8 * kk + tig + 4) * 72 + gid;
#pragma unroll
            for (int nt = 0; nt < 8; nt++)
                mma_f16_k16(s[nt], aq[kk], kr0[8 * nt], kr1[8 * nt]);
        }

        float mx0 = -1e30f, mx1 = -1e30f;
#pragma unroll
        for (int nt = 0; nt < 8; nt++) {
            mx0 = fmaxf(mx0, fmaxf(s[nt][0], s[nt][1]));
            mx1 = fmaxf(mx1, fmaxf(s[nt][2], s[nt][3]));
        }
        mx0 = fmaxf(mx0, __shfl_xor_sync(0xffffffffu, mx0, 1));
        mx0 = fmaxf(mx0, __shfl_xor_sync(0xffffffffu, mx0, 2));
        mx1 = fmaxf(mx1, __shfl_xor_sync(0xffffffffu, mx1, 1));
        mx1 = fmaxf(mx1, __shfl_xor_sync(0xffffffffu, mx1, 2));

        float mn0 = fmaxf(rm0, mx0), mn1 = fmaxf(rm1, mx1);
        float al0 = __expf(rm0 - mn0), al1 = __expf(rm1 - mn1);
        rm0 = mn0; rm1 = mn1;

        float rs0 = 0.f, rs1 = 0.f;
#pragma unroll
        for (int nt = 0; nt < 8; nt++) {
            float p0 = __expf(s[nt][0] - mn0);
            float p1 = __expf(s[nt][1] - mn0);
            float p2 = __expf(s[nt][2] - mn1);
            float p3 = __expf(s[nt][3] - mn1);
            rs0 += p0 + p1; rs1 += p2 + p3;
            __half2 h01 = __floats2half2_rn(p0, p1);
            __half2 h23 = __floats2half2_rn(p2, p3);
            Pw[gid * 36 + 4 * nt + tig] = *(uint32_t*)&h01;
            Pw[(gid + 8) * 36 + 4 * nt + tig] = *(uint32_t*)&h23;
        }
        rs0 += __shfl_xor_sync(0xffffffffu, rs0, 1);
        rs0 += __shfl_xor_sync(0xffffffffu, rs0, 2);
        rs1 += __shfl_xor_sync(0xffffffffu, rs1, 1);
        rs1 += __shfl_xor_sync(0xffffffffu, rs1, 2);
        rl0 = rl0 * al0 + rs0;
        rl1 = rl1 * al1 + rs1;

#pragma unroll
        for (int nt = 0; nt < 8; nt++) {
            o[nt][0] *= al0; o[nt][1] *= al0;
            o[nt][2] *= al1; o[nt][3] *= al1;
        }
        __syncwarp();

#pragma unroll
        for (int kk = 0; kk < 4; kk++) {
            uint32_t pa[4];
            pa[0] = Pw[gid * 36 + 8 * kk + tig];
            pa[1] = Pw[(gid + 8) * 36 + 8 * kk + tig];
            pa[2] = Pw[gid * 36 + 8 * kk + tig + 4];
            pa[3] = Pw[(gid + 8) * 36 + 8 * kk + tig + 4];
            const uint32_t* gr0 = Gs2 + (8 * kk + tig) * 72 + gid;
            const uint32_t* gr1 = Gs2 + (8 * kk + tig + 4) * 72 + gid;
#pragma unroll
            for (int nt = 0; nt < 8; nt++)
                mma_f16_k16(o[nt], pa, gr0[8 * nt], gr1[8 * nt]);
        }

        if (pre) {
            uint32_t* nK = KG + ((jt + 1) & 1) * 4608;
#pragma unroll
            for (int r = 0; r < 2; r++) {
                *(uint4*)(nK + pr_row[r] * 72 + pr_m4[r]) = pk[r];
                *(uint4*)(nK + 2304 + pr_row[r] * 72 + pr_m4[r]) = pg[r];
            }
        }
        __syncthreads();
    }

    // ---- fused epilogue: y as half2 c-pairs; z = W*y + Wb + x ----
    float li0 = 1.f / rl0, li1 = 1.f / rl1;
    uint32_t* Ys = Ps;
#pragma unroll
    for (int nt = 0; nt < 8; nt++) {
        __half2 h01 = __floats2half2_rn(o[nt][0] * li0, o[nt][1] * li0);
        __half2 h23 = __floats2half2_rn(o[nt][2] * li1, o[nt][3] * li1);
        Ys[(w * 16 + gid) * 36 + 4 * nt + tig] = *(uint32_t*)&h01;
        Ys[(w * 16 + gid + 8) * 36 + 4 * nt + tig] = *(uint32_t*)&h23;
    }
    for (int i = tid; i < 2048; i += 256) {
        int kp = i >> 6, oc = i & 63;
        KG[kp * 72 + oc] = W1p[i];
    }
    __syncthreads();

    float d[8][4];
#pragma unroll
    for (int nt = 0; nt < 8; nt++)
#pragma unroll
        for (int r = 0; r < 4; r++) d[nt][r] = 0.f;
#pragma unroll
    for (int kk = 0; kk < 4; kk++) {
        uint32_t pa[4];
        pa[0] = Ys[(w * 16 + gid) * 36 + 8 * kk + tig];
        pa[1] = Ys[(w * 16 + gid + 8) * 36 + 8 * kk + tig];
        pa[2] = Ys[(w * 16 + gid) * 36 + 8 * kk + tig + 4];
        pa[3] = Ys[(w * 16 + gid + 8) * 36 + 8 * kk + tig + 4];
        const uint32_t* wr0 = KG + (8 * kk + tig) * 72 + gid;
        const uint32_t* wr1 = KG + (8 * kk + tig + 4) * 72 + gid;
#pragma unroll
        for (int nt = 0; nt < 8; nt++)
            mma_f16_k16(d[nt], pa, wr0[8 * nt], wr1[8 * nt]);
    }

#pragma unroll
    for (int nt = 0; nt < 8; nt++) {
        int oc0 = 8 * nt + 2 * tig;
        float b0 = W1b[oc0], b1 = W1b[oc0 + 1];
        int n  = n0 + w * 16 + gid;
        size_t x0 = (((size_t)(b * CC + oc0)) << 12);
        float z0 = d[nt][0] + b0 + x[x0 + n];
        float z1 = d[nt][1] + b1 + x[x0 + 4096 + n];
        float z2 = d[nt][2] + b0 + x[x0 + n + 8];
        float z3 = d[nt][3] + b1 + x[x0 + 4096 + n + 8];
        __half2 h01 = __floats2half2_rn(z0, z1);
        __half2 h23 = __floats2half2_rn(z2, z3);
        size_t zbase = (((size_t)(b * 32 + 4 * nt + tig)) << 12);
        zp[zbase + n]     = *(uint32_t*)&h01;
        zp[zbase + n + 8] = *(uint32_t*)&h23;
    }
}
#define FLASH_SMEM (55296)

// ---------------- driver -----------------------------------------------------
extern "C" void kernel_launch(void* const* d_in, const int* in_sizes, int n_in,
                              void* d_out, int out_size)
{
    const float* x       = (const float*)d_in[0];
    const float* conv1_w = (const float*)d_in[1];
    const float* bn1_g   = (const float*)d_in[2];
    const float* bn1_b   = (const float*)d_in[3];
    const float* theta_w = (const float*)d_in[4];
    const float* theta_b = (const float*)d_in[5];
    const float* phi_w   = (const float*)d_in[6];
    const float* phi_b   = (const float*)d_in[7];
    const float* g_w     = (const float*)d_in[8];
    const float* g_b     = (const float*)d_in[9];
    const float* W_w     = (const float*)d_in[10];
    const float* W_b     = (const float*)d_in[11];
    const float* conv2_w = (const float*)d_in[12];
    const float* bn2_g   = (const float*)d_in[13];
    const float* bn2_b   = (const float*)d_in[14];
    float* out = (float*)d_out;

    float* buf = nullptr;
    cudaGetSymbolAddress((void**)&buf, g_buf);
    float*    raw   = buf + OFF_RAW;
    uint32_t* th2   = (uint32_t*)(buf + OFF_TH2);
    uint32_t* ph2   = (uint32_t*)(buf + OFF_PH2);
    uint32_t* gp2   = (uint32_t*)(buf + OFF_GP2);
    uint32_t* x1p   = (uint32_t*)(buf + OFF_X1P);
    uint32_t* zp    = (uint32_t*)(buf + OFF_ZP);
    uint32_t* wpbuf = (uint32_t*)(buf + OFF_WP);
    float*    part1 = buf + OFF_PT1;
    float*    part2 = buf + OFF_PT2;

    cudaFuncSetAttribute(conv3x3_f16_kernel,
                         cudaFuncAttributeMaxDynamicSharedMemorySize, CONV_SMEM);
    cudaFuncSetAttribute(flash_fused_kernel,
                         cudaFuncAttributeMaxDynamicSharedMemorySize, FLASH_SMEM);

    // weight prep (5 conv sets + W1x1) + zero stats partials
    wtrans_f16_kernel<<<408, 256>>>(conv1_w, theta_w, phi_w, g_w, conv2_w, W_w,
                                    wpbuf, part1);

    // conv1 (fp32 input, fused BN stats) -> BN apply + ReLU + pack
    conv3x3_f16_kernel<<<dim3(32, BB, 1), 256, CONV_SMEM>>>(
        x, wpbuf, nullptr, nullptr, nullptr, raw, raw, raw, 0, 1, part1);
    bn_apply_relu_pack_kernel<<<2048, 256>>>(raw, part1, bn1_g, bn1_b, x1p);

    // theta (mode1), phi (mode2), g (mode3) in one launch
    conv3x3_f16_kernel<<<dim3(32, BB, 3), 256, CONV_SMEM>>>(
        x1p, wpbuf + 20480, theta_b, phi_b, g_b,
        th2, ph2, gp2, 1 | (2 << 8) | (3 << 16), 0, nullptr);

    // attention + fused 1x1 W conv + residual -> zp
    flash_fused_kernel<<<dim3(NN / 128, BB), 256, FLASH_SMEM>>>(
        th2, ph2, gp2, wpbuf + 102400, W_b, x, zp);

    // conv2 (fused BN stats) -> BN apply + ReLU -> out
    conv3x3_f16_kernel<<<dim3(32, BB, 1), 256, CONV_SMEM>>>(
        zp, wpbuf + 4 * 20480, nullptr, nullptr, nullptr, raw, raw, raw, 0, 0, part2);
    bn_apply_relu_kernel<<<1024, 256>>>((const float4*)raw, part2, bn2_g, bn2_b,
                                        (float4*)out);
}